// round 1
// baseline (speedup 1.0000x reference)
#include <cuda_runtime.h>
#include <math.h>

#define NB 2
#define NS 2048
#define ND 1024
#define NH 16
#define NDH 64
#define NBH (NB*NH)          // 32
#define NTOK (NB*NS)         // 4096
#define NELEM (NTOK*ND)      // 4194304

// Scratch (head-major layout: [(b*NH+h)*NS + s]*NDH + d)
__device__ float g_Q[NELEM];
__device__ float g_V[NELEM];
__device__ float g_V1[NELEM];
__device__ float g_K1[NELEM];

// ---------------------------------------------------------------------------
// GEMM: C = A @ W^T  (A: 4096x1024, W: 1024x1024 row-major), written head-major.
// blockIdx.z selects {Q, V, V1}. BM=BN=64, BK=16, 256 threads, 4x4 per thread.
// Since BN==DH==64, each n-tile is exactly one head -> contiguous head-major rows.
// ---------------------------------------------------------------------------
__global__ __launch_bounds__(256) void gemm3_kernel(
    const float* __restrict__ x, const float* __restrict__ y,
    const float* __restrict__ wq, const float* __restrict__ wv,
    const float* __restrict__ wo)
{
    __shared__ __align__(16) float As[16][64];
    __shared__ __align__(16) float Ws[16][64];

    const float* A; const float* W; float* C;
    switch (blockIdx.z) {
        case 0:  A = x; W = wq; C = g_Q;  break;
        case 1:  A = y; W = wv; C = g_V;  break;
        default: A = x; W = wo; C = g_V1; break;
    }
    const int m0  = blockIdx.y * 64;
    const int n0  = blockIdx.x * 64;
    const int tid = threadIdx.x;
    const int ty  = tid >> 4, tx = tid & 15;
    const int lr  = tid >> 2;       // 0..63: row within tile (coalesced loads)
    const int lc  = tid & 3;        // 0..3 : float4 chunk of the 16-wide k slab

    float acc[4][4] = {};

    for (int k0 = 0; k0 < ND; k0 += 16) {
        float4 av  = *(const float4*)&A[(size_t)(m0 + lr) * ND + k0 + lc * 4];
        float4 wv4 = *(const float4*)&W[(size_t)(n0 + lr) * ND + k0 + lc * 4];
        As[lc*4+0][lr] = av.x;  As[lc*4+1][lr] = av.y;
        As[lc*4+2][lr] = av.z;  As[lc*4+3][lr] = av.w;
        Ws[lc*4+0][lr] = wv4.x; Ws[lc*4+1][lr] = wv4.y;
        Ws[lc*4+2][lr] = wv4.z; Ws[lc*4+3][lr] = wv4.w;
        __syncthreads();
#pragma unroll
        for (int kk = 0; kk < 16; kk++) {
            float4 a4 = *(const float4*)&As[kk][ty * 4];
            float4 w4 = *(const float4*)&Ws[kk][tx * 4];
            float a[4] = {a4.x, a4.y, a4.z, a4.w};
            float w[4] = {w4.x, w4.y, w4.z, w4.w};
#pragma unroll
            for (int i = 0; i < 4; i++)
#pragma unroll
                for (int j = 0; j < 4; j++)
                    acc[i][j] += a[i] * w[j];
        }
        __syncthreads();
    }

    const int h     = blockIdx.x;          // head index
    const int b     = m0 / NS;             // whole tile within one batch
    const int sbase = (m0 % NS) + ty * 4;
#pragma unroll
    for (int i = 0; i < 4; i++) {
        float4 o = make_float4(acc[i][0], acc[i][1], acc[i][2], acc[i][3]);
        *(float4*)&C[(((size_t)b * NH + h) * NS + sbase + i) * NDH + tx * 4] = o;
    }
}

// ---------------------------------------------------------------------------
// RoPE: rope Q in place; k_roped = rope(y_head) -> k_ret (the 2nd output!);
// k1 = rope(k_roped) -> g_K1. One thread per (b,h,s,pair i in 0..31).
// ---------------------------------------------------------------------------
__global__ __launch_bounds__(256) void rope_kernel(
    const float* __restrict__ y, float* __restrict__ k_ret)
{
    const int idx = blockIdx.x * 256 + threadIdx.x;   // NBH*NS*32 = 2097152 exact
    const int i   = idx & 31;
    const int s   = (idx >> 5) & (NS - 1);
    const int bh  = idx >> 16;
    const int b   = bh >> 4, h = bh & 15;

    const float LOG2_THETA = 13.287712379549449f;     // log2(10000)
    const float freq = exp2f(-(float)i * (LOG2_THETA * (1.0f / 32.0f)));
    float sn, cs;
    sincosf((float)s * freq, &sn, &cs);

    const size_t base = ((size_t)bh * NS + s) * NDH;

    // Q in-place (single rope)
    float q1 = g_Q[base + i], q2 = g_Q[base + i + 32];
    g_Q[base + i]      = q1 * cs - q2 * sn;
    g_Q[base + i + 32] = q2 * cs + q1 * sn;

    // K = y (no projection); single rope -> k_ret; double rope -> g_K1
    const float* yrow = y + ((size_t)b * NS + s) * ND + h * NDH;
    float u1 = yrow[i], u2 = yrow[i + 32];
    float kr1 = u1 * cs - u2 * sn;
    float kr2 = u2 * cs + u1 * sn;
    k_ret[base + i]      = kr1;
    k_ret[base + i + 32] = kr2;
    g_K1[base + i]       = kr1 * cs - kr2 * sn;
    g_K1[base + i + 32]  = kr2 * cs + kr1 * sn;
}

// ---------------------------------------------------------------------------
// Flash-style causal attention + one extra diagonal (k1,v1) element per row.
// Block = 64 queries of one (b,h); 256 threads as 16x16, each owns a 4x4 of
// every 64x64 tile. Online softmax state (m,l) lives in registers, replicated
// across the 16 lanes of each row-group via shuffle reductions.
// ---------------------------------------------------------------------------
__global__ __launch_bounds__(256) void attn_kernel(
    const float* __restrict__ Kr, float* __restrict__ out)
{
    extern __shared__ __align__(16) float sm[];
    float* Qs = sm;            // [64][64] queries (natural)
    float* KT = sm + 4096;     // [64][64] K transposed [d][c] (reused natural for K1)
    float* Vs = sm + 8192;     // [64][64] V natural [c][d]    (reused for V1)
    float* Ps = sm + 12288;    // [64][64] probabilities

    const int qt  = blockIdx.x;
    const int bh  = blockIdx.y;
    const int tid = threadIdx.x;
    const int ty  = tid >> 4, tx = tid & 15;

    const float* Qg  = g_Q + ((size_t)bh * NS + qt * 64) * NDH;
    const float* Krg = Kr  + (size_t)bh * NS * NDH;
    const float* Vg  = g_V + (size_t)bh * NS * NDH;

#pragma unroll
    for (int t = 0; t < 4; t++) {
        int i4 = tid + t * 256;
        *(float4*)&Qs[i4 * 4] = *(const float4*)&Qg[i4 * 4];
    }

    float m_[4], l_[4], O[4][4];
#pragma unroll
    for (int i = 0; i < 4; i++) {
        m_[i] = -1e30f; l_[i] = 0.f;
#pragma unroll
        for (int j = 0; j < 4; j++) O[i][j] = 0.f;
    }

    for (int jt = 0; jt <= qt; jt++) {
        __syncthreads();   // previous iteration done reading Ps/Vs/KT
        const float* ksrc = Krg + (size_t)jt * 64 * NDH;
        const float* vsrc = Vg  + (size_t)jt * 64 * NDH;
#pragma unroll
        for (int t = 0; t < 4; t++) {
            int i4 = tid + t * 256;
            int c = i4 >> 4, d4 = i4 & 15;
            float4 v = *(const float4*)&ksrc[i4 * 4];   // == [c][d4*4]
            KT[(d4*4+0)*64 + c] = v.x;
            KT[(d4*4+1)*64 + c] = v.y;
            KT[(d4*4+2)*64 + c] = v.z;
            KT[(d4*4+3)*64 + c] = v.w;
            *(float4*)&Vs[i4 * 4] = *(const float4*)&vsrc[i4 * 4];
        }
        __syncthreads();

        // S = Q @ K^T (64x64x64)
        float s[4][4] = {};
#pragma unroll 16
        for (int d = 0; d < 64; d++) {
            float4 k4 = *(const float4*)&KT[d * 64 + tx * 4];
            float q0 = Qs[(ty*4+0)*64 + d];
            float q1 = Qs[(ty*4+1)*64 + d];
            float q2 = Qs[(ty*4+2)*64 + d];
            float q3 = Qs[(ty*4+3)*64 + d];
            s[0][0] += q0*k4.x; s[0][1] += q0*k4.y; s[0][2] += q0*k4.z; s[0][3] += q0*k4.w;
            s[1][0] += q1*k4.x; s[1][1] += q1*k4.y; s[1][2] += q1*k4.z; s[1][3] += q1*k4.w;
            s[2][0] += q2*k4.x; s[2][1] += q2*k4.y; s[2][2] += q2*k4.z; s[2][3] += q2*k4.w;
            s[3][0] += q3*k4.x; s[3][1] += q3*k4.y; s[3][2] += q3*k4.z; s[3][3] += q3*k4.w;
        }

        const bool diag = (jt == qt);
#pragma unroll
        for (int i = 0; i < 4; i++) {
            const int row = ty * 4 + i;
            float mx = -1e30f;
#pragma unroll
            for (int j = 0; j < 4; j++) {
                float sv = s[i][j] * 0.125f;
                if (diag && (tx * 4 + j > row)) sv = -1e30f;   // causal within tile
                s[i][j] = sv;
                mx = fmaxf(mx, sv);
            }
#pragma unroll
            for (int o = 8; o > 0; o >>= 1)
                mx = fmaxf(mx, __shfl_xor_sync(0xffffffffu, mx, o));
            const float mnew = fmaxf(m_[i], mx);
            const float sc   = __expf(m_[i] - mnew);
            float ps = 0.f;
#pragma unroll
            for (int j = 0; j < 4; j++) {
                float p = __expf(s[i][j] - mnew);
                s[i][j] = p; ps += p;
            }
#pragma unroll
            for (int o = 8; o > 0; o >>= 1)
                ps += __shfl_xor_sync(0xffffffffu, ps, o);
            l_[i] = l_[i] * sc + ps;
            m_[i] = mnew;
#pragma unroll
            for (int j = 0; j < 4; j++) O[i][j] *= sc;
            *(float4*)&Ps[row * 64 + tx * 4] = make_float4(s[i][0], s[i][1], s[i][2], s[i][3]);
        }
        __syncthreads();

        // O += P @ V (64x64x64)
#pragma unroll 16
        for (int c = 0; c < 64; c++) {
            float4 v4 = *(const float4*)&Vs[c * 64 + tx * 4];
            float p0 = Ps[(ty*4+0)*64 + c];
            float p1 = Ps[(ty*4+1)*64 + c];
            float p2 = Ps[(ty*4+2)*64 + c];
            float p3 = Ps[(ty*4+3)*64 + c];
            O[0][0] += p0*v4.x; O[0][1] += p0*v4.y; O[0][2] += p0*v4.z; O[0][3] += p0*v4.w;
            O[1][0] += p1*v4.x; O[1][1] += p1*v4.y; O[1][2] += p1*v4.z; O[1][3] += p1*v4.w;
            O[2][0] += p2*v4.x; O[2][1] += p2*v4.y; O[2][2] += p2*v4.z; O[2][3] += p2*v4.w;
            O[3][0] += p3*v4.x; O[3][1] += p3*v4.y; O[3][2] += p3*v4.z; O[3][3] += p3*v4.w;
        }
    }

    // Extra diagonal bank: score q_i . k1_i, value v1_i, then normalize.
    __syncthreads();
    const float* k1src = g_K1 + ((size_t)bh * NS + qt * 64) * NDH;
    const float* v1src = g_V1 + ((size_t)bh * NS + qt * 64) * NDH;
#pragma unroll
    for (int t = 0; t < 4; t++) {
        int i4 = tid + t * 256;
        *(float4*)&KT[i4 * 4] = *(const float4*)&k1src[i4 * 4];   // natural layout now
        *(float4*)&Vs[i4 * 4] = *(const float4*)&v1src[i4 * 4];
    }
    __syncthreads();

    const int b = bh >> 4, h = bh & 15;
#pragma unroll
    for (int i = 0; i < 4; i++) {
        const int row = ty * 4 + i;
        float4 q4 = *(const float4*)&Qs[row * 64 + tx * 4];
        float4 k4 = *(const float4*)&KT[row * 64 + tx * 4];
        float part = q4.x*k4.x + q4.y*k4.y + q4.z*k4.z + q4.w*k4.w;
#pragma unroll
        for (int o = 8; o > 0; o >>= 1)
            part += __shfl_xor_sync(0xffffffffu, part, o);
        const float s2 = part * 0.125f;
        const float mf = fmaxf(m_[i], s2);
        const float sc = __expf(m_[i] - mf);
        const float p2 = __expf(s2 - mf);
        const float inv = 1.0f / (l_[i] * sc + p2);
        float4 v4 = *(const float4*)&Vs[row * 64 + tx * 4];
        float4 o4;
        o4.x = (O[i][0] * sc + p2 * v4.x) * inv;
        o4.y = (O[i][1] * sc + p2 * v4.y) * inv;
        o4.z = (O[i][2] * sc + p2 * v4.z) * inv;
        o4.w = (O[i][3] * sc + p2 * v4.w) * inv;
        *(float4*)&out[((size_t)b * NS + qt * 64 + row) * ND + h * NDH + tx * 4] = o4;
    }
}

// ---------------------------------------------------------------------------
extern "C" void kernel_launch(void* const* d_in, const int* in_sizes, int n_in,
                              void* d_out, int out_size)
{
    const float* x  = (const float*)d_in[0];
    const float* y  = (const float*)d_in[1];
    const float* wq = (const float*)d_in[2];
    // d_in[3] = wk is UNUSED by the reference (K = y directly)
    const float* wv = (const float*)d_in[4];
    const float* wo = (const float*)d_in[5];

    float* out   = (float*)d_out;          // (B,S,D)   = 4194304 floats
    float* k_ret = out + NELEM;            // (B,H,S,DH)= 4194304 floats

    cudaFuncSetAttribute(attn_kernel,
                         cudaFuncAttributeMaxDynamicSharedMemorySize, 65536);

    gemm3_kernel<<<dim3(16, 64, 3), 256>>>(x, y, wq, wv, wo);
    rope_kernel<<<(NBH * NS * 32) / 256, 256>>>(y, k_ret);
    attn_kernel<<<dim3(NS / 64, NBH), 256, 65536>>>(k_ret, out);
}

// round 2
// speedup vs baseline: 1.7179x; 1.7179x over previous
#include <cuda_runtime.h>
#include <math.h>

#define NB 2
#define NS 2048
#define ND 1024
#define NH 16
#define NDH 64
#define NBH (NB*NH)          // 32
#define NTOK (NB*NS)         // 4096
#define NELEM (NTOK*ND)      // 4194304

// Scratch (head-major layout: [(b*NH+h)*NS + s]*NDH + d)
__device__ float g_Q[NELEM];
__device__ float g_V[NELEM];
__device__ float g_V1[NELEM];
__device__ float g_K1[NELEM];

// ---------------------------------------------------------------------------
// GEMM: C = A @ W^T (A: 4096x1024, W: 1024x1024 row-major), written head-major.
// blockIdx.z selects {Q, V, V1}. BM=BN=128, BK=16, 256 threads, 8x8 per thread.
// ---------------------------------------------------------------------------
__global__ __launch_bounds__(256, 2) void gemm3_kernel(
    const float* __restrict__ x, const float* __restrict__ y,
    const float* __restrict__ wq, const float* __restrict__ wv,
    const float* __restrict__ wo)
{
    __shared__ __align__(16) float As[16][128];
    __shared__ __align__(16) float Ws[16][128];

    const float* A; const float* W; float* C;
    switch (blockIdx.z) {
        case 0:  A = x; W = wq; C = g_Q;  break;
        case 1:  A = y; W = wv; C = g_V;  break;
        default: A = x; W = wo; C = g_V1; break;
    }
    const int m0  = blockIdx.y * 128;
    const int n0  = blockIdx.x * 128;
    const int tid = threadIdx.x;
    const int ty  = tid >> 4, tx = tid & 15;
    const int lr  = tid >> 1;            // 0..127 row within tile
    const int lc  = (tid & 1) * 8;       // 0 or 8: k-offset of this thread's 8 floats

    float acc[8][8] = {};

    const float* Arow = A + (size_t)(m0 + lr) * ND + lc;
    const float* Wrow = W + (size_t)(n0 + lr) * ND + lc;

    for (int k0 = 0; k0 < ND; k0 += 16) {
        float4 a0 = *(const float4*)&Arow[k0];
        float4 a1 = *(const float4*)&Arow[k0 + 4];
        float4 w0 = *(const float4*)&Wrow[k0];
        float4 w1 = *(const float4*)&Wrow[k0 + 4];
        __syncthreads();
        As[lc+0][lr]=a0.x; As[lc+1][lr]=a0.y; As[lc+2][lr]=a0.z; As[lc+3][lr]=a0.w;
        As[lc+4][lr]=a1.x; As[lc+5][lr]=a1.y; As[lc+6][lr]=a1.z; As[lc+7][lr]=a1.w;
        Ws[lc+0][lr]=w0.x; Ws[lc+1][lr]=w0.y; Ws[lc+2][lr]=w0.z; Ws[lc+3][lr]=w0.w;
        Ws[lc+4][lr]=w1.x; Ws[lc+5][lr]=w1.y; Ws[lc+6][lr]=w1.z; Ws[lc+7][lr]=w1.w;
        __syncthreads();
#pragma unroll
        for (int kk = 0; kk < 16; kk++) {
            float4 av0 = *(const float4*)&As[kk][ty * 8];
            float4 av1 = *(const float4*)&As[kk][ty * 8 + 4];
            float4 wv0 = *(const float4*)&Ws[kk][tx * 8];
            float4 wv1 = *(const float4*)&Ws[kk][tx * 8 + 4];
            float a[8] = {av0.x,av0.y,av0.z,av0.w, av1.x,av1.y,av1.z,av1.w};
            float w[8] = {wv0.x,wv0.y,wv0.z,wv0.w, wv1.x,wv1.y,wv1.z,wv1.w};
#pragma unroll
            for (int i = 0; i < 8; i++)
#pragma unroll
                for (int j = 0; j < 8; j++)
                    acc[i][j] += a[i] * w[j];
        }
    }

    // Head-major store: columns n0+tx*8+j; head = 2*blockIdx.x + (tx>>3)
    const int b     = m0 / NS;
    const int sbase = (m0 % NS) + ty * 8;
    const int h     = blockIdx.x * 2 + (tx >> 3);
    const int dbase = (tx & 7) * 8;
    float* Cb = C + (((size_t)b * NH + h) * NS) * NDH + dbase;
#pragma unroll
    for (int i = 0; i < 8; i++) {
        const size_t off = (size_t)(sbase + i) * NDH;
        *(float4*)&Cb[off]     = make_float4(acc[i][0], acc[i][1], acc[i][2], acc[i][3]);
        *(float4*)&Cb[off + 4] = make_float4(acc[i][4], acc[i][5], acc[i][6], acc[i][7]);
    }
}

// ---------------------------------------------------------------------------
// RoPE: rope Q in place; k_roped = rope(y_head) -> k_ret (the 2nd output);
// k1 = rope(k_roped) -> g_K1. One thread per (b,h,s,pair i in 0..31).
// ---------------------------------------------------------------------------
__global__ __launch_bounds__(256) void rope_kernel(
    const float* __restrict__ y, float* __restrict__ k_ret)
{
    const int idx = blockIdx.x * 256 + threadIdx.x;
    const int i   = idx & 31;
    const int s   = (idx >> 5) & (NS - 1);
    const int bh  = idx >> 16;
    const int b   = bh >> 4, h = bh & 15;

    const float LOG2_THETA = 13.287712379549449f;     // log2(10000)
    const float freq = exp2f(-(float)i * (LOG2_THETA * (1.0f / 32.0f)));
    float sn, cs;
    sincosf((float)s * freq, &sn, &cs);

    const size_t base = ((size_t)bh * NS + s) * NDH;

    float q1 = g_Q[base + i], q2 = g_Q[base + i + 32];
    g_Q[base + i]      = q1 * cs - q2 * sn;
    g_Q[base + i + 32] = q2 * cs + q1 * sn;

    const float* yrow = y + ((size_t)b * NS + s) * ND + h * NDH;
    float u1 = yrow[i], u2 = yrow[i + 32];
    float kr1 = u1 * cs - u2 * sn;
    float kr2 = u2 * cs + u1 * sn;
    k_ret[base + i]      = kr1;
    k_ret[base + i + 32] = kr2;
    g_K1[base + i]       = kr1 * cs - kr2 * sn;
    g_K1[base + i + 32]  = kr2 * cs + kr1 * sn;
}

// ---------------------------------------------------------------------------
// Flash-style causal attention + one extra diagonal (k1,v1) element per row.
// Block = 128 queries of one (b,h); 256 threads as 16x16; each thread owns
// an 8x4 fragment of every 128x64 score tile. Online softmax in registers,
// replicated across 16 lanes via xor-shuffles.
// ---------------------------------------------------------------------------
__global__ __launch_bounds__(256, 2) void attn_kernel(
    const float* __restrict__ Kr, float* __restrict__ out)
{
    extern __shared__ __align__(16) float sm[];
    float* Qs = sm;             // [128][64] queries, natural
    float* KT = sm + 8192;      // [64][64]  K transposed [d][c]
    float* Vs = sm + 12288;     // [64][64]  V natural [c][d]
    float* Ps = sm + 16384;     // [128][64] probabilities
    // epilogue reuse: K1 tile -> sm+8192 (8192 floats), V1 tile -> Ps

    const int qt  = blockIdx.x;           // 0..15 (128-row query tiles)
    const int bh  = blockIdx.y;
    const int tid = threadIdx.x;
    const int ty  = tid >> 4, tx = tid & 15;

    const float* Qg  = g_Q + ((size_t)bh * NS + qt * 128) * NDH;
    const float* Krg = Kr  + (size_t)bh * NS * NDH;
    const float* Vg  = g_V + (size_t)bh * NS * NDH;

#pragma unroll
    for (int t = 0; t < 8; t++) {
        int i4 = tid + t * 256;
        *(float4*)&Qs[i4 * 4] = *(const float4*)&Qg[i4 * 4];
    }

    float m_[8], l_[8], O[8][4];
#pragma unroll
    for (int i = 0; i < 8; i++) {
        m_[i] = -1e30f; l_[i] = 0.f;
#pragma unroll
        for (int j = 0; j < 4; j++) O[i][j] = 0.f;
    }

    const int jt_end = 2 * qt + 1;
    for (int jt = 0; jt <= jt_end; jt++) {
        __syncthreads();   // previous iteration done reading KT/Vs/Ps
        const float* ksrc = Krg + (size_t)jt * 64 * NDH;
        const float* vsrc = Vg  + (size_t)jt * 64 * NDH;
#pragma unroll
        for (int t = 0; t < 4; t++) {
            int i4 = tid + t * 256;
            int c = i4 >> 4, d4 = i4 & 15;
            float4 v = *(const float4*)&ksrc[i4 * 4];
            KT[(d4*4+0)*64 + c] = v.x;
            KT[(d4*4+1)*64 + c] = v.y;
            KT[(d4*4+2)*64 + c] = v.z;
            KT[(d4*4+3)*64 + c] = v.w;
            *(float4*)&Vs[i4 * 4] = *(const float4*)&vsrc[i4 * 4];
        }
        __syncthreads();

        // S = Q @ K^T : 128x64x64, 8x4 per thread, d in chunks of 4
        float s[8][4] = {};
#pragma unroll 4
        for (int d = 0; d < 64; d += 4) {
            float4 k0 = *(const float4*)&KT[(d+0)*64 + tx*4];
            float4 k1 = *(const float4*)&KT[(d+1)*64 + tx*4];
            float4 k2 = *(const float4*)&KT[(d+2)*64 + tx*4];
            float4 k3 = *(const float4*)&KT[(d+3)*64 + tx*4];
#pragma unroll
            for (int i = 0; i < 8; i++) {
                float4 q = *(const float4*)&Qs[(ty*8+i)*64 + d];
                s[i][0] += q.x*k0.x + q.y*k1.x + q.z*k2.x + q.w*k3.x;
                s[i][1] += q.x*k0.y + q.y*k1.y + q.z*k2.y + q.w*k3.y;
                s[i][2] += q.x*k0.z + q.y*k1.z + q.z*k2.z + q.w*k3.z;
                s[i][3] += q.x*k0.w + q.y*k1.w + q.z*k2.w + q.w*k3.w;
            }
        }

        const bool boundary = (jt >= 2 * qt);
#pragma unroll
        for (int i = 0; i < 8; i++) {
            const int row  = ty * 8 + i;
            const int grow = qt * 128 + row;
            float mx = -1e30f;
#pragma unroll
            for (int j = 0; j < 4; j++) {
                float sv = s[i][j] * 0.125f;
                if (boundary && (jt * 64 + tx * 4 + j > grow)) sv = -1e30f;
                s[i][j] = sv;
                mx = fmaxf(mx, sv);
            }
#pragma unroll
            for (int o = 8; o > 0; o >>= 1)
                mx = fmaxf(mx, __shfl_xor_sync(0xffffffffu, mx, o));
            const float mnew = fmaxf(m_[i], mx);
            const float sc   = __expf(m_[i] - mnew);
            float ps = 0.f;
#pragma unroll
            for (int j = 0; j < 4; j++) {
                float p = __expf(s[i][j] - mnew);
                s[i][j] = p; ps += p;
            }
#pragma unroll
            for (int o = 8; o > 0; o >>= 1)
                ps += __shfl_xor_sync(0xffffffffu, ps, o);
            l_[i] = l_[i] * sc + ps;
            m_[i] = mnew;
#pragma unroll
            for (int j = 0; j < 4; j++) O[i][j] *= sc;
            *(float4*)&Ps[row * 64 + tx * 4] =
                make_float4(s[i][0], s[i][1], s[i][2], s[i][3]);
        }
        __syncthreads();

        // O += P @ V : 128x64x64, c in chunks of 4
#pragma unroll 4
        for (int c = 0; c < 64; c += 4) {
            float4 v0 = *(const float4*)&Vs[(c+0)*64 + tx*4];
            float4 v1 = *(const float4*)&Vs[(c+1)*64 + tx*4];
            float4 v2 = *(const float4*)&Vs[(c+2)*64 + tx*4];
            float4 v3 = *(const float4*)&Vs[(c+3)*64 + tx*4];
#pragma unroll
            for (int i = 0; i < 8; i++) {
                float4 p = *(const float4*)&Ps[(ty*8+i)*64 + c];
                O[i][0] += p.x*v0.x + p.y*v1.x + p.z*v2.x + p.w*v3.x;
                O[i][1] += p.x*v0.y + p.y*v1.y + p.z*v2.y + p.w*v3.y;
                O[i][2] += p.x*v0.z + p.y*v1.z + p.z*v2.z + p.w*v3.z;
                O[i][3] += p.x*v0.w + p.y*v1.w + p.z*v2.w + p.w*v3.w;
            }
        }
    }

    // Extra diagonal bank: score q_i . k1_i, value v1_i, then normalize.
    __syncthreads();
    float* K1s = sm + 8192;    // 128x64, reuses KT+Vs
    float* V1s = Ps;           // 128x64
    const float* k1src = g_K1 + ((size_t)bh * NS + qt * 128) * NDH;
    const float* v1src = g_V1 + ((size_t)bh * NS + qt * 128) * NDH;
#pragma unroll
    for (int t = 0; t < 8; t++) {
        int i4 = tid + t * 256;
        *(float4*)&K1s[i4 * 4] = *(const float4*)&k1src[i4 * 4];
        *(float4*)&V1s[i4 * 4] = *(const float4*)&v1src[i4 * 4];
    }
    __syncthreads();

    const int b = bh >> 4, h = bh & 15;
#pragma unroll
    for (int i = 0; i < 8; i++) {
        const int row = ty * 8 + i;
        float4 q4 = *(const float4*)&Qs[row * 64 + tx * 4];
        float4 k4 = *(const float4*)&K1s[row * 64 + tx * 4];
        float part = q4.x*k4.x + q4.y*k4.y + q4.z*k4.z + q4.w*k4.w;
#pragma unroll
        for (int o = 8; o > 0; o >>= 1)
            part += __shfl_xor_sync(0xffffffffu, part, o);
        const float s2 = part * 0.125f;
        const float mf = fmaxf(m_[i], s2);
        const float sc = __expf(m_[i] - mf);
        const float p2 = __expf(s2 - mf);
        const float inv = 1.0f / (l_[i] * sc + p2);
        float4 v4 = *(const float4*)&V1s[row * 64 + tx * 4];
        float4 o4;
        o4.x = (O[i][0] * sc + p2 * v4.x) * inv;
        o4.y = (O[i][1] * sc + p2 * v4.y) * inv;
        o4.z = (O[i][2] * sc + p2 * v4.z) * inv;
        o4.w = (O[i][3] * sc + p2 * v4.w) * inv;
        *(float4*)&out[((size_t)b * NS + qt * 128 + row) * ND + h * NDH + tx * 4] = o4;
    }
}

// ---------------------------------------------------------------------------
extern "C" void kernel_launch(void* const* d_in, const int* in_sizes, int n_in,
                              void* d_out, int out_size)
{
    const float* x  = (const float*)d_in[0];
    const float* y  = (const float*)d_in[1];
    const float* wq = (const float*)d_in[2];
    // d_in[3] = wk is UNUSED by the reference (K = y directly)
    const float* wv = (const float*)d_in[4];
    const float* wo = (const float*)d_in[5];

    float* out   = (float*)d_out;          // (B,S,D)    = 4194304 floats
    float* k_ret = out + NELEM;            // (B,H,S,DH) = 4194304 floats

    cudaFuncSetAttribute(attn_kernel,
                         cudaFuncAttributeMaxDynamicSharedMemorySize, 98304);

    gemm3_kernel<<<dim3(8, 32, 3), 256>>>(x, y, wq, wv, wo);
    rope_kernel<<<(NBH * NS * 32) / 256, 256>>>(y, k_ret);
    attn_kernel<<<dim3(NS / 128, NBH), 256, 98304>>>(k_ret, out);
}

// round 4
// speedup vs baseline: 2.1117x; 1.2292x over previous
#include <cuda_runtime.h>
#include <cuda_bf16.h>
#include <math.h>
#include <cstdint>

#define NB 2
#define NS 2048
#define ND 1024
#define NH 16
#define NDH 64
#define NBH (NB*NH)          // 32
#define NTOK (NB*NS)         // 4096
#define NELEM (NTOK*ND)      // 4194304

// Scratch (head-major layout: [(b*NH+h)*NS + s]*NDH + d)
__device__ float g_Q[NELEM];
__device__ float g_V[NELEM];
__device__ float g_V1[NELEM];
__device__ float g_K1[NELEM];

// ===========================================================================
// mma.sync helpers (baseline PTX — works on plain compute_103 target)
// ===========================================================================
__device__ __forceinline__ uint32_t smem_u32(const void* p) {
    uint32_t a;
    asm("{ .reg .u64 t; cvta.to.shared.u64 t, %1; cvt.u32.u64 %0, t; }"
        : "=r"(a) : "l"(p));
    return a;
}
__device__ __forceinline__ void ldsm4(uint32_t r[4], uint32_t addr) {
    asm volatile("ldmatrix.sync.aligned.m8n8.x4.shared.b16 {%0,%1,%2,%3}, [%4];"
                 : "=r"(r[0]), "=r"(r[1]), "=r"(r[2]), "=r"(r[3]) : "r"(addr));
}
__device__ __forceinline__ void mma_bf16(float d[4], const uint32_t a[4],
                                         const uint32_t b[2]) {
    asm volatile(
        "mma.sync.aligned.m16n8k16.row.col.f32.bf16.bf16.f32 "
        "{%0,%1,%2,%3}, {%4,%5,%6,%7}, {%8,%9}, {%0,%1,%2,%3};"
        : "+f"(d[0]), "+f"(d[1]), "+f"(d[2]), "+f"(d[3])
        : "r"(a[0]), "r"(a[1]), "r"(a[2]), "r"(a[3]), "r"(b[0]), "r"(b[1]));
}
// Split a float4 into hi/lo bf16x4 packed as uint2 each.
__device__ __forceinline__ void split4(float4 v, uint2& hi, uint2& lo) {
    __nv_bfloat16 hx = __float2bfloat16_rn(v.x);
    __nv_bfloat16 hy = __float2bfloat16_rn(v.y);
    __nv_bfloat16 hz = __float2bfloat16_rn(v.z);
    __nv_bfloat16 hw = __float2bfloat16_rn(v.w);
    hi.x = (uint32_t)__bfloat16_as_ushort(hx) | ((uint32_t)__bfloat16_as_ushort(hy) << 16);
    hi.y = (uint32_t)__bfloat16_as_ushort(hz) | ((uint32_t)__bfloat16_as_ushort(hw) << 16);
    __nv_bfloat16 lx = __float2bfloat16_rn(v.x - __bfloat162float(hx));
    __nv_bfloat16 ly = __float2bfloat16_rn(v.y - __bfloat162float(hy));
    __nv_bfloat16 lz = __float2bfloat16_rn(v.z - __bfloat162float(hz));
    __nv_bfloat16 lw = __float2bfloat16_rn(v.w - __bfloat162float(hw));
    lo.x = (uint32_t)__bfloat16_as_ushort(lx) | ((uint32_t)__bfloat16_as_ushort(ly) << 16);
    lo.y = (uint32_t)__bfloat16_as_ushort(lz) | ((uint32_t)__bfloat16_as_ushort(lw) << 16);
}

// ===========================================================================
// Tensor-core GEMM (mma.sync): C = A @ W^T, fp32 in/out.
// bf16 2-term split, 3 passes (hi*hi + lo*hi + hi*lo) -> fp32-grade accuracy.
// Block tile 128x128, 8 warps (4m x 2n), warp tile 32x64, k-step 32.
// smem rows padded to 40 bf16 (80B): (r*5+c)%8 distinct -> conflict-free ldsm.
// blockIdx.z selects {Q, V, V1}; output written head-major.
// ===========================================================================
#define LDS_ROW 40   // bf16 per smem row (32 data + 8 pad) = 80 bytes

__global__ __launch_bounds__(256) void gemm3_mma_kernel(
    const float* __restrict__ x, const float* __restrict__ y,
    const float* __restrict__ wq, const float* __restrict__ wv,
    const float* __restrict__ wo)
{
    __shared__ __align__(16) __nv_bfloat16 sAhi[128][LDS_ROW];
    __shared__ __align__(16) __nv_bfloat16 sAlo[128][LDS_ROW];
    __shared__ __align__(16) __nv_bfloat16 sWhi[128][LDS_ROW];
    __shared__ __align__(16) __nv_bfloat16 sWlo[128][LDS_ROW];

    const float* A; const float* W; float* C;
    switch (blockIdx.z) {
        case 0:  A = x; W = wq; C = g_Q;  break;
        case 1:  A = y; W = wv; C = g_V;  break;
        default: A = x; W = wo; C = g_V1; break;
    }
    const int m0   = blockIdx.y * 128;
    const int n0   = blockIdx.x * 128;
    const int tid  = threadIdx.x;
    const int lane = tid & 31, wid = tid >> 5;
    const int wm   = wid >> 1, wn = wid & 1;

    const uint32_t bAhi = smem_u32(sAhi), bAlo = smem_u32(sAlo);
    const uint32_t bWhi = smem_u32(sWhi), bWlo = smem_u32(sWlo);

    // ldmatrix per-lane address components
    const uint32_t lrow16 = (uint32_t)(lane & 15);      // row within 16-row block
    const uint32_t lchunk = (uint32_t)(lane >> 4) * 16; // 16B chunk within k16

    float acc[2][8][4];
#pragma unroll
    for (int i = 0; i < 2; i++)
#pragma unroll
        for (int j = 0; j < 8; j++)
#pragma unroll
            for (int r = 0; r < 4; r++) acc[i][j][r] = 0.f;

    // global-load mapping: idx = tid + i*256 -> row = idx>>3 (0..127), c = idx&7
    const int grow = tid >> 3;          // row for i=0 (rows advance by 32 per i)
    const int gc   = tid & 7;           // float4 index within 32-float k slab

    float4 pa[4], pw[4];
#pragma unroll
    for (int i = 0; i < 4; i++) {
        pa[i] = *(const float4*)&A[(size_t)(m0 + grow + i * 32) * ND + gc * 4];
        pw[i] = *(const float4*)&W[(size_t)(n0 + grow + i * 32) * ND + gc * 4];
    }

    for (int k0 = 0; k0 < ND; k0 += 32) {
        __syncthreads();   // smem free (previous compute done)
#pragma unroll
        for (int i = 0; i < 4; i++) {
            const int row = grow + i * 32;
            uint2 hi, lo;
            split4(pa[i], hi, lo);
            *(uint2*)&sAhi[row][gc * 4] = hi;
            *(uint2*)&sAlo[row][gc * 4] = lo;
            split4(pw[i], hi, lo);
            *(uint2*)&sWhi[row][gc * 4] = hi;
            *(uint2*)&sWlo[row][gc * 4] = lo;
        }
        __syncthreads();

        if (k0 + 32 < ND) {
#pragma unroll
            for (int i = 0; i < 4; i++) {
                pa[i] = *(const float4*)&A[(size_t)(m0 + grow + i * 32) * ND + k0 + 32 + gc * 4];
                pw[i] = *(const float4*)&W[(size_t)(n0 + grow + i * 32) * ND + k0 + 32 + gc * 4];
            }
        }

#pragma unroll
        for (int ks = 0; ks < 2; ks++) {
            const uint32_t kb = (uint32_t)ks * 32 + lchunk;  // byte offset of k16 chunk
            uint32_t ahi[2][4], alo[2][4], bw[8][2], t[4];

            // ---- load A hi + W hi ----
#pragma unroll
            for (int fm = 0; fm < 2; fm++) {
                uint32_t r = (uint32_t)(wm * 32 + fm * 16) + lrow16;
                ldsm4(ahi[fm], bAhi + r * (LDS_ROW * 2) + kb);
            }
#pragma unroll
            for (int fb = 0; fb < 4; fb++) {
                uint32_t r = (uint32_t)(wn * 64 + fb * 16) + lrow16;
                ldsm4(t, bWhi + r * (LDS_ROW * 2) + kb);
                bw[2*fb][0]   = t[0]; bw[2*fb][1]   = t[2];
                bw[2*fb+1][0] = t[1]; bw[2*fb+1][1] = t[3];
            }
            // pass 1: Ahi * Whi
#pragma unroll
            for (int fm = 0; fm < 2; fm++)
#pragma unroll
                for (int fn = 0; fn < 8; fn++)
                    mma_bf16(acc[fm][fn], ahi[fm], bw[fn]);

            // ---- pass 2: Alo * Whi ----
#pragma unroll
            for (int fm = 0; fm < 2; fm++) {
                uint32_t r = (uint32_t)(wm * 32 + fm * 16) + lrow16;
                ldsm4(alo[fm], bAlo + r * (LDS_ROW * 2) + kb);
            }
#pragma unroll
            for (int fm = 0; fm < 2; fm++)
#pragma unroll
                for (int fn = 0; fn < 8; fn++)
                    mma_bf16(acc[fm][fn], alo[fm], bw[fn]);

            // ---- pass 3: Ahi * Wlo ----
#pragma unroll
            for (int fb = 0; fb < 4; fb++) {
                uint32_t r = (uint32_t)(wn * 64 + fb * 16) + lrow16;
                ldsm4(t, bWlo + r * (LDS_ROW * 2) + kb);
                bw[2*fb][0]   = t[0]; bw[2*fb][1]   = t[2];
                bw[2*fb+1][0] = t[1]; bw[2*fb+1][1] = t[3];
            }
#pragma unroll
            for (int fm = 0; fm < 2; fm++)
#pragma unroll
                for (int fn = 0; fn < 8; fn++)
                    mma_bf16(acc[fm][fn], ahi[fm], bw[fn]);
        }
    }

    // Epilogue: head-major store. d-frag layout: rows g,g+8; cols 2t,2t+1.
    const int g  = lane >> 2;
    const int t2 = (lane & 3) * 2;
    const int bb = m0 >> 11;                      // batch
    const int h  = blockIdx.x * 2 + wn;           // head
    float* Cb = C + ((size_t)(bb * NH + h) * NS) * NDH;
    const int srow0 = (m0 & (NS - 1)) + wm * 32 + g;
#pragma unroll
    for (int fm = 0; fm < 2; fm++) {
        const int s = srow0 + fm * 16;
#pragma unroll
        for (int fn = 0; fn < 8; fn++) {
            const int d = fn * 8 + t2;
            *(float2*)&Cb[(size_t)s * NDH + d]       = make_float2(acc[fm][fn][0], acc[fm][fn][1]);
            *(float2*)&Cb[(size_t)(s + 8) * NDH + d] = make_float2(acc[fm][fn][2], acc[fm][fn][3]);
        }
    }
}

// ---------------------------------------------------------------------------
// RoPE: rope Q in place; k_roped = rope(y_head) -> k_ret (the 2nd output);
// k1 = rope(k_roped) -> g_K1. One thread per (b,h,s,pair i in 0..31).
// ---------------------------------------------------------------------------
__global__ __launch_bounds__(256) void rope_kernel(
    const float* __restrict__ y, float* __restrict__ k_ret)
{
    const int idx = blockIdx.x * 256 + threadIdx.x;
    const int i   = idx & 31;
    const int s   = (idx >> 5) & (NS - 1);
    const int bh  = idx >> 16;
    const int b   = bh >> 4, h = bh & 15;

    const float LOG2_THETA = 13.287712379549449f;     // log2(10000)
    const float freq = exp2f(-(float)i * (LOG2_THETA * (1.0f / 32.0f)));
    float sn, cs;
    sincosf((float)s * freq, &sn, &cs);

    const size_t base = ((size_t)bh * NS + s) * NDH;

    float q1 = g_Q[base + i], q2 = g_Q[base + i + 32];
    g_Q[base + i]      = q1 * cs - q2 * sn;
    g_Q[base + i + 32] = q2 * cs + q1 * sn;

    const float* yrow = y + ((size_t)b * NS + s) * ND + h * NDH;
    float u1 = yrow[i], u2 = yrow[i + 32];
    float kr1 = u1 * cs - u2 * sn;
    float kr2 = u2 * cs + u1 * sn;
    k_ret[base + i]      = kr1;
    k_ret[base + i + 32] = kr2;
    g_K1[base + i]       = kr1 * cs - kr2 * sn;
    g_K1[base + i + 32]  = kr2 * cs + kr1 * sn;
}

// ---------------------------------------------------------------------------
// Flash-style causal attention + one extra diagonal (k1,v1) element per row.
// ---------------------------------------------------------------------------
__global__ __launch_bounds__(256, 2) void attn_kernel(
    const float* __restrict__ Kr, float* __restrict__ out)
{
    extern __shared__ __align__(16) float sm[];
    float* Qs = sm;             // [128][64]
    float* KT = sm + 8192;      // [64][64] transposed
    float* Vs = sm + 12288;     // [64][64]
    float* Ps = sm + 16384;     // [128][64]

    const int qt  = blockIdx.x;
    const int bh  = blockIdx.y;
    const int tid = threadIdx.x;
    const int ty  = tid >> 4, tx = tid & 15;

    const float* Qg  = g_Q + ((size_t)bh * NS + qt * 128) * NDH;
    const float* Krg = Kr  + (size_t)bh * NS * NDH;
    const float* Vg  = g_V + (size_t)bh * NS * NDH;

#pragma unroll
    for (int t = 0; t < 8; t++) {
        int i4 = tid + t * 256;
        *(float4*)&Qs[i4 * 4] = *(const float4*)&Qg[i4 * 4];
    }

    float m_[8], l_[8], O[8][4];
#pragma unroll
    for (int i = 0; i < 8; i++) {
        m_[i] = -1e30f; l_[i] = 0.f;
#pragma unroll
        for (int j = 0; j < 4; j++) O[i][j] = 0.f;
    }

    const int jt_end = 2 * qt + 1;
    for (int jt = 0; jt <= jt_end; jt++) {
        __syncthreads();
        const float* ksrc = Krg + (size_t)jt * 64 * NDH;
        const float* vsrc = Vg  + (size_t)jt * 64 * NDH;
#pragma unroll
        for (int t = 0; t < 4; t++) {
            int i4 = tid + t * 256;
            int c = i4 >> 4, d4 = i4 & 15;
            float4 v = *(const float4*)&ksrc[i4 * 4];
            KT[(d4*4+0)*64 + c] = v.x;
            KT[(d4*4+1)*64 + c] = v.y;
            KT[(d4*4+2)*64 + c] = v.z;
            KT[(d4*4+3)*64 + c] = v.w;
            *(float4*)&Vs[i4 * 4] = *(const float4*)&vsrc[i4 * 4];
        }
        __syncthreads();

        float s[8][4] = {};
#pragma unroll 4
        for (int d = 0; d < 64; d += 4) {
            float4 k0 = *(const float4*)&KT[(d+0)*64 + tx*4];
            float4 k1 = *(const float4*)&KT[(d+1)*64 + tx*4];
            float4 k2 = *(const float4*)&KT[(d+2)*64 + tx*4];
            float4 k3 = *(const float4*)&KT[(d+3)*64 + tx*4];
#pragma unroll
            for (int i = 0; i < 8; i++) {
                float4 q = *(const float4*)&Qs[(ty*8+i)*64 + d];
                s[i][0] += q.x*k0.x + q.y*k1.x + q.z*k2.x + q.w*k3.x;
                s[i][1] += q.x*k0.y + q.y*k1.y + q.z*k2.y + q.w*k3.y;
                s[i][2] += q.x*k0.z + q.y*k1.z + q.z*k2.z + q.w*k3.z;
                s[i][3] += q.x*k0.w + q.y*k1.w + q.z*k2.w + q.w*k3.w;
            }
        }

        const bool boundary = (jt >= 2 * qt);
#pragma unroll
        for (int i = 0; i < 8; i++) {
            const int row  = ty * 8 + i;
            const int grow = qt * 128 + row;
            float mx = -1e30f;
#pragma unroll
            for (int j = 0; j < 4; j++) {
                float sv = s[i][j] * 0.125f;
                if (boundary && (jt * 64 + tx * 4 + j > grow)) sv = -1e30f;
                s[i][j] = sv;
                mx = fmaxf(mx, sv);
            }
#pragma unroll
            for (int o = 8; o > 0; o >>= 1)
                mx = fmaxf(mx, __shfl_xor_sync(0xffffffffu, mx, o));
            const float mnew = fmaxf(m_[i], mx);
            const float sc   = __expf(m_[i] - mnew);
            float ps = 0.f;
#pragma unroll
            for (int j = 0; j < 4; j++) {
                float p = __expf(s[i][j] - mnew);
                s[i][j] = p; ps += p;
            }
#pragma unroll
            for (int o = 8; o > 0; o >>= 1)
                ps += __shfl_xor_sync(0xffffffffu, ps, o);
            l_[i] = l_[i] * sc + ps;
            m_[i] = mnew;
#pragma unroll
            for (int j = 0; j < 4; j++) O[i][j] *= sc;
            *(float4*)&Ps[row * 64 + tx * 4] =
                make_float4(s[i][0], s[i][1], s[i][2], s[i][3]);
        }
        __syncthreads();

#pragma unroll 4
        for (int c = 0; c < 64; c += 4) {
            float4 v0 = *(const float4*)&Vs[(c+0)*64 + tx*4];
            float4 v1 = *(const float4*)&Vs[(c+1)*64 + tx*4];
            float4 v2 = *(const float4*)&Vs[(c+2)*64 + tx*4];
            float4 v3 = *(const float4*)&Vs[(c+3)*64 + tx*4];
#pragma unroll
            for (int i = 0; i < 8; i++) {
                float4 p = *(const float4*)&Ps[(ty*8+i)*64 + c];
                O[i][0] += p.x*v0.x + p.y*v1.x + p.z*v2.x + p.w*v3.x;
                O[i][1] += p.x*v0.y + p.y*v1.y + p.z*v2.y + p.w*v3.y;
                O[i][2] += p.x*v0.z + p.y*v1.z + p.z*v2.z + p.w*v3.z;
                O[i][3] += p.x*v0.w + p.y*v1.w + p.z*v2.w + p.w*v3.w;
            }
        }
    }

    __syncthreads();
    float* K1s = sm + 8192;
    float* V1s = Ps;
    const float* k1src = g_K1 + ((size_t)bh * NS + qt * 128) * NDH;
    const float* v1src = g_V1 + ((size_t)bh * NS + qt * 128) * NDH;
#pragma unroll
    for (int t = 0; t < 8; t++) {
        int i4 = tid + t * 256;
        *(float4*)&K1s[i4 * 4] = *(const float4*)&k1src[i4 * 4];
        *(float4*)&V1s[i4 * 4] = *(const float4*)&v1src[i4 * 4];
    }
    __syncthreads();

    const int b = bh >> 4, h = bh & 15;
#pragma unroll
    for (int i = 0; i < 8; i++) {
        const int row = ty * 8 + i;
        float4 q4 = *(const float4*)&Qs[row * 64 + tx * 4];
        float4 k4 = *(const float4*)&K1s[row * 64 + tx * 4];
        float part = q4.x*k4.x + q4.y*k4.y + q4.z*k4.z + q4.w*k4.w;
#pragma unroll
        for (int o = 8; o > 0; o >>= 1)
            part += __shfl_xor_sync(0xffffffffu, part, o);
        const float s2 = part * 0.125f;
        const float mf = fmaxf(m_[i], s2);
        const float sc = __expf(m_[i] - mf);
        const float p2 = __expf(s2 - mf);
        const float inv = 1.0f / (l_[i] * sc + p2);
        float4 v4 = *(const float4*)&V1s[row * 64 + tx * 4];
        float4 o4;
        o4.x = (O[i][0] * sc + p2 * v4.x) * inv;
        o4.y = (O[i][1] * sc + p2 * v4.y) * inv;
        o4.z = (O[i][2] * sc + p2 * v4.z) * inv;
        o4.w = (O[i][3] * sc + p2 * v4.w) * inv;
        *(float4*)&out[((size_t)b * NS + qt * 128 + row) * ND + h * NDH + tx * 4] = o4;
    }
}

// ---------------------------------------------------------------------------
extern "C" void kernel_launch(void* const* d_in, const int* in_sizes, int n_in,
                              void* d_out, int out_size)
{
    const float* x  = (const float*)d_in[0];
    const float* y  = (const float*)d_in[1];
    const float* wq = (const float*)d_in[2];
    // d_in[3] = wk is UNUSED by the reference (K = y directly)
    const float* wv = (const float*)d_in[4];
    const float* wo = (const float*)d_in[5];

    float* out   = (float*)d_out;          // (B,S,D)    = 4194304 floats
    float* k_ret = out + NELEM;            // (B,H,S,DH) = 4194304 floats

    cudaFuncSetAttribute(attn_kernel,
                         cudaFuncAttributeMaxDynamicSharedMemorySize, 98304);

    gemm3_mma_kernel<<<dim3(8, 32, 3), 256>>>(x, y, wq, wv, wo);
    rope_kernel<<<(NBH * NS * 32) / 256, 256>>>(y, k_ret);
    attn_kernel<<<dim3(NS / 128, NBH), 256, 98304>>>(k_ret, out);
}

// round 6
// speedup vs baseline: 3.2292x; 1.5292x over previous
#include <cuda_runtime.h>
#include <cuda_bf16.h>
#include <math.h>
#include <cstdint>

#define NB 2
#define NS 2048
#define ND 1024
#define NH 16
#define NDH 64
#define NBH (NB*NH)          // 32
#define NTOK (NB*NS)         // 4096
#define NELEM (NTOK*ND)      // 4194304

// Scratch (head-major layout: [(b*NH+h)*NS + s]*NDH + d)
__device__ float g_Q[NELEM];
__device__ float g_V[NELEM];
__device__ float g_V1[NELEM];
__device__ float g_K1[NELEM];

// ===========================================================================
// mma.sync helpers (baseline PTX — works on plain compute_103 target)
// ===========================================================================
__device__ __forceinline__ uint32_t smem_u32(const void* p) {
    uint32_t a;
    asm("{ .reg .u64 t; cvta.to.shared.u64 t, %1; cvt.u32.u64 %0, t; }"
        : "=r"(a) : "l"(p));
    return a;
}
__device__ __forceinline__ void ldsm4(uint32_t r[4], uint32_t addr) {
    asm volatile("ldmatrix.sync.aligned.m8n8.x4.shared.b16 {%0,%1,%2,%3}, [%4];"
                 : "=r"(r[0]), "=r"(r[1]), "=r"(r[2]), "=r"(r[3]) : "r"(addr));
}
__device__ __forceinline__ void mma_bf16(float d[4], const uint32_t a[4],
                                         const uint32_t b[2]) {
    asm volatile(
        "mma.sync.aligned.m16n8k16.row.col.f32.bf16.bf16.f32 "
        "{%0,%1,%2,%3}, {%4,%5,%6,%7}, {%8,%9}, {%0,%1,%2,%3};"
        : "+f"(d[0]), "+f"(d[1]), "+f"(d[2]), "+f"(d[3])
        : "r"(a[0]), "r"(a[1]), "r"(a[2]), "r"(a[3]), "r"(b[0]), "r"(b[1]));
}
// Split a float4 into hi/lo bf16x4 packed as uint2 each.
__device__ __forceinline__ void split4(float4 v, uint2& hi, uint2& lo) {
    __nv_bfloat16 hx = __float2bfloat16_rn(v.x);
    __nv_bfloat16 hy = __float2bfloat16_rn(v.y);
    __nv_bfloat16 hz = __float2bfloat16_rn(v.z);
    __nv_bfloat16 hw = __float2bfloat16_rn(v.w);
    hi.x = (uint32_t)__bfloat16_as_ushort(hx) | ((uint32_t)__bfloat16_as_ushort(hy) << 16);
    hi.y = (uint32_t)__bfloat16_as_ushort(hz) | ((uint32_t)__bfloat16_as_ushort(hw) << 16);
    __nv_bfloat16 lx = __float2bfloat16_rn(v.x - __bfloat162float(hx));
    __nv_bfloat16 ly = __float2bfloat16_rn(v.y - __bfloat162float(hy));
    __nv_bfloat16 lz = __float2bfloat16_rn(v.z - __bfloat162float(hz));
    __nv_bfloat16 lw = __float2bfloat16_rn(v.w - __bfloat162float(hw));
    lo.x = (uint32_t)__bfloat16_as_ushort(lx) | ((uint32_t)__bfloat16_as_ushort(ly) << 16);
    lo.y = (uint32_t)__bfloat16_as_ushort(lz) | ((uint32_t)__bfloat16_as_ushort(lw) << 16);
}
__device__ __forceinline__ uint32_t pack_bf16(float a, float b) {
    __nv_bfloat162 h = __floats2bfloat162_rn(a, b);   // a -> low, b -> high
    return *(uint32_t*)&h;
}
// Split two floats into packed hi bf16x2 and lo bf16x2.
__device__ __forceinline__ void split2_pack(float a, float b,
                                            uint32_t& hi, uint32_t& lo) {
    __nv_bfloat16 ha = __float2bfloat16_rn(a);
    __nv_bfloat16 hb = __float2bfloat16_rn(b);
    hi = (uint32_t)__bfloat16_as_ushort(ha) | ((uint32_t)__bfloat16_as_ushort(hb) << 16);
    __nv_bfloat16 la = __float2bfloat16_rn(a - __bfloat162float(ha));
    __nv_bfloat16 lb = __float2bfloat16_rn(b - __bfloat162float(hb));
    lo = (uint32_t)__bfloat16_as_ushort(la) | ((uint32_t)__bfloat16_as_ushort(lb) << 16);
}
// FFMA-only exp (avoids MUFU bottleneck). Valid for x <= ~0; ~2e-6 rel err.
__device__ __forceinline__ float fast_exp(float x) {
    float y = fmaxf(x * 1.4426950408889634f, -126.0f);
    float z = y + 12582912.0f;                 // round-to-nearest int
    int   n = __float_as_int(z) - 0x4B400000;
    float r = y - (z - 12582912.0f);           // r in [-0.5, 0.5]
    float p = 1.3333558146e-3f;
    p = fmaf(p, r, 9.6181291076e-3f);
    p = fmaf(p, r, 5.5504108664e-2f);
    p = fmaf(p, r, 2.4022650695e-1f);
    p = fmaf(p, r, 6.9314718056e-1f);
    p = fmaf(p, r, 1.0f);
    return p * __int_as_float((n + 127) << 23);
}

// ===========================================================================
// Tensor-core GEMM (mma.sync): C = A @ W^T, fp32 in/out.
// bf16 2-term split, 3 passes (hi*hi + lo*hi + hi*lo) -> fp32-grade accuracy.
// ===========================================================================
#define LDS_ROW 40   // bf16 per smem row (32 data + 8 pad) = 80 bytes

__global__ __launch_bounds__(256) void gemm3_mma_kernel(
    const float* __restrict__ x, const float* __restrict__ y,
    const float* __restrict__ wq, const float* __restrict__ wv,
    const float* __restrict__ wo)
{
    __shared__ __align__(16) __nv_bfloat16 sAhi[128][LDS_ROW];
    __shared__ __align__(16) __nv_bfloat16 sAlo[128][LDS_ROW];
    __shared__ __align__(16) __nv_bfloat16 sWhi[128][LDS_ROW];
    __shared__ __align__(16) __nv_bfloat16 sWlo[128][LDS_ROW];

    const float* A; const float* W; float* C;
    switch (blockIdx.z) {
        case 0:  A = x; W = wq; C = g_Q;  break;
        case 1:  A = y; W = wv; C = g_V;  break;
        default: A = x; W = wo; C = g_V1; break;
    }
    const int m0   = blockIdx.y * 128;
    const int n0   = blockIdx.x * 128;
    const int tid  = threadIdx.x;
    const int lane = tid & 31, wid = tid >> 5;
    const int wm   = wid >> 1, wn = wid & 1;

    const uint32_t bAhi = smem_u32(sAhi), bAlo = smem_u32(sAlo);
    const uint32_t bWhi = smem_u32(sWhi), bWlo = smem_u32(sWlo);

    const uint32_t lrow16 = (uint32_t)(lane & 15);
    const uint32_t lchunk = (uint32_t)(lane >> 4) * 16;

    float acc[2][8][4];
#pragma unroll
    for (int i = 0; i < 2; i++)
#pragma unroll
        for (int j = 0; j < 8; j++)
#pragma unroll
            for (int r = 0; r < 4; r++) acc[i][j][r] = 0.f;

    const int grow = tid >> 3;
    const int gc   = tid & 7;

    float4 pa4[4], pw4[4];
#pragma unroll
    for (int i = 0; i < 4; i++) {
        pa4[i] = *(const float4*)&A[(size_t)(m0 + grow + i * 32) * ND + gc * 4];
        pw4[i] = *(const float4*)&W[(size_t)(n0 + grow + i * 32) * ND + gc * 4];
    }

    for (int k0 = 0; k0 < ND; k0 += 32) {
        __syncthreads();
#pragma unroll
        for (int i = 0; i < 4; i++) {
            const int row = grow + i * 32;
            uint2 hi, lo;
            split4(pa4[i], hi, lo);
            *(uint2*)&sAhi[row][gc * 4] = hi;
            *(uint2*)&sAlo[row][gc * 4] = lo;
            split4(pw4[i], hi, lo);
            *(uint2*)&sWhi[row][gc * 4] = hi;
            *(uint2*)&sWlo[row][gc * 4] = lo;
        }
        __syncthreads();

        if (k0 + 32 < ND) {
#pragma unroll
            for (int i = 0; i < 4; i++) {
                pa4[i] = *(const float4*)&A[(size_t)(m0 + grow + i * 32) * ND + k0 + 32 + gc * 4];
                pw4[i] = *(const float4*)&W[(size_t)(n0 + grow + i * 32) * ND + k0 + 32 + gc * 4];
            }
        }

#pragma unroll
        for (int ks = 0; ks < 2; ks++) {
            const uint32_t kb = (uint32_t)ks * 32 + lchunk;
            uint32_t ahi[2][4], alo[2][4], bw[8][2], t[4];

#pragma unroll
            for (int fm = 0; fm < 2; fm++) {
                uint32_t r = (uint32_t)(wm * 32 + fm * 16) + lrow16;
                ldsm4(ahi[fm], bAhi + r * (LDS_ROW * 2) + kb);
            }
#pragma unroll
            for (int fb = 0; fb < 4; fb++) {
                uint32_t r = (uint32_t)(wn * 64 + fb * 16) + lrow16;
                ldsm4(t, bWhi + r * (LDS_ROW * 2) + kb);
                bw[2*fb][0]   = t[0]; bw[2*fb][1]   = t[2];
                bw[2*fb+1][0] = t[1]; bw[2*fb+1][1] = t[3];
            }
#pragma unroll
            for (int fm = 0; fm < 2; fm++)
#pragma unroll
                for (int fn = 0; fn < 8; fn++)
                    mma_bf16(acc[fm][fn], ahi[fm], bw[fn]);

#pragma unroll
            for (int fm = 0; fm < 2; fm++) {
                uint32_t r = (uint32_t)(wm * 32 + fm * 16) + lrow16;
                ldsm4(alo[fm], bAlo + r * (LDS_ROW * 2) + kb);
            }
#pragma unroll
            for (int fm = 0; fm < 2; fm++)
#pragma unroll
                for (int fn = 0; fn < 8; fn++)
                    mma_bf16(acc[fm][fn], alo[fm], bw[fn]);

#pragma unroll
            for (int fb = 0; fb < 4; fb++) {
                uint32_t r = (uint32_t)(wn * 64 + fb * 16) + lrow16;
                ldsm4(t, bWlo + r * (LDS_ROW * 2) + kb);
                bw[2*fb][0]   = t[0]; bw[2*fb][1]   = t[2];
                bw[2*fb+1][0] = t[1]; bw[2*fb+1][1] = t[3];
            }
#pragma unroll
            for (int fm = 0; fm < 2; fm++)
#pragma unroll
                for (int fn = 0; fn < 8; fn++)
                    mma_bf16(acc[fm][fn], ahi[fm], bw[fn]);
        }
    }

    const int g  = lane >> 2;
    const int t2 = (lane & 3) * 2;
    const int bb = m0 >> 11;
    const int h  = blockIdx.x * 2 + wn;
    float* Cb = C + ((size_t)(bb * NH + h) * NS) * NDH;
    const int srow0 = (m0 & (NS - 1)) + wm * 32 + g;
#pragma unroll
    for (int fm = 0; fm < 2; fm++) {
        const int s = srow0 + fm * 16;
#pragma unroll
        for (int fn = 0; fn < 8; fn++) {
            const int d = fn * 8 + t2;
            *(float2*)&Cb[(size_t)s * NDH + d]       = make_float2(acc[fm][fn][0], acc[fm][fn][1]);
            *(float2*)&Cb[(size_t)(s + 8) * NDH + d] = make_float2(acc[fm][fn][2], acc[fm][fn][3]);
        }
    }
}

// ---------------------------------------------------------------------------
// RoPE: rope Q in place; k_roped -> k_ret; k1 = rope(k_roped) -> g_K1.
// ---------------------------------------------------------------------------
__global__ __launch_bounds__(256) void rope_kernel(
    const float* __restrict__ y, float* __restrict__ k_ret)
{
    const int idx = blockIdx.x * 256 + threadIdx.x;
    const int i   = idx & 31;
    const int s   = (idx >> 5) & (NS - 1);
    const int bh  = idx >> 16;
    const int b   = bh >> 4, h = bh & 15;

    const float LOG2_THETA = 13.287712379549449f;
    const float freq = exp2f(-(float)i * (LOG2_THETA * (1.0f / 32.0f)));
    float sn, cs;
    sincosf((float)s * freq, &sn, &cs);

    const size_t base = ((size_t)bh * NS + s) * NDH;

    float q1 = g_Q[base + i], q2 = g_Q[base + i + 32];
    g_Q[base + i]      = q1 * cs - q2 * sn;
    g_Q[base + i + 32] = q2 * cs + q1 * sn;

    const float* yrow = y + ((size_t)b * NS + s) * ND + h * NDH;
    float u1 = yrow[i], u2 = yrow[i + 32];
    float kr1 = u1 * cs - u2 * sn;
    float kr2 = u2 * cs + u1 * sn;
    k_ret[base + i]      = kr1;
    k_ret[base + i + 32] = kr2;
    g_K1[base + i]       = kr1 * cs - kr2 * sn;
    g_K1[base + i + 32]  = kr2 * cs + kr1 * sn;
}

// ===========================================================================
// MMA flash attention + diagonal (k1,v1) bank.
// CTA = 128 queries of one (b,h); 8 warps, each m16 x n64.
// QK^T: 3-pass bf16 split. PV: 3-pass split (Phi*Vhi + Plo*Vhi + Phi*Vlo).
// smem (bf16, row stride 72 elems = 144B, conflict-free ldmatrix).
// ===========================================================================
#define QHI_B 0
#define QLO_B 18432
#define KHI_B 36864
#define KLO_B 46080
#define VHI_B 55296
#define VLO_B 64512
#define ATTN_SMEM 73728

__global__ __launch_bounds__(256) void attn_mma_kernel(
    const float* __restrict__ Kr, float* __restrict__ out)
{
    extern __shared__ __align__(16) char smraw[];
    __nv_bfloat16* sb = (__nv_bfloat16*)smraw;

    const int qt  = (NS / 128 - 1) - blockIdx.x;   // heavy tiles first
    const int bh  = blockIdx.y;
    const int tid = threadIdx.x;
    const int lane = tid & 31, wid = tid >> 5;
    const int g = lane >> 2, t2 = (lane & 3) * 2;
    const uint32_t lrow16 = (uint32_t)(lane & 15);
    const uint32_t lchunk = (uint32_t)(lane >> 4) * 16;
    const uint32_t sbase = smem_u32(sb);

    // ---- Q tile -> smem bf16 hi/lo, scale 1/8 folded in ----
    const float* Qg = g_Q + ((size_t)bh * NS + qt * 128) * NDH;
#pragma unroll
    for (int i = 0; i < 8; i++) {
        int idx = tid + i * 256;            // 2048 float4
        int row = idx >> 4, c4 = idx & 15;
        float4 v = *(const float4*)&Qg[idx * 4];
        v.x *= 0.125f; v.y *= 0.125f; v.z *= 0.125f; v.w *= 0.125f;
        uint2 hi, lo; split4(v, hi, lo);
        *(uint2*)((char*)sb + QHI_B + row * 144 + c4 * 8) = hi;
        *(uint2*)((char*)sb + QLO_B + row * 144 + c4 * 8) = lo;
    }

    float m0 = -1e30f, m1 = -1e30f, l0 = 0.f, l1 = 0.f;
    float O[8][4];
#pragma unroll
    for (int fn = 0; fn < 8; fn++)
#pragma unroll
        for (int j = 0; j < 4; j++) O[fn][j] = 0.f;

    const float* Kg = Kr  + (size_t)bh * NS * NDH;
    const float* Vg = g_V + (size_t)bh * NS * NDH;
    const int jt_end = 2 * qt + 1;

    for (int jt = 0; jt <= jt_end; jt++) {
        __syncthreads();
        const float* ks = Kg + (size_t)jt * 64 * NDH;
        const float* vs = Vg + (size_t)jt * 64 * NDH;
#pragma unroll
        for (int i = 0; i < 4; i++) {
            int idx = tid + i * 256;        // 1024 float4
            int row = idx >> 4, c4 = idx & 15;
            float4 kv = *(const float4*)&ks[idx * 4];
            uint2 hi, lo; split4(kv, hi, lo);
            *(uint2*)((char*)sb + KHI_B + row * 144 + c4 * 8) = hi;
            *(uint2*)((char*)sb + KLO_B + row * 144 + c4 * 8) = lo;
            float4 vv = *(const float4*)&vs[idx * 4];
            float vals[4] = {vv.x, vv.y, vv.z, vv.w};
#pragma unroll
            for (int j = 0; j < 4; j++) {
                int d = c4 * 4 + j;
                __nv_bfloat16 h = __float2bfloat16_rn(vals[j]);
                sb[VHI_B/2 + d * 72 + row] = h;
                sb[VLO_B/2 + d * 72 + row] =
                    __float2bfloat16_rn(vals[j] - __bfloat162float(h));
            }
        }
        __syncthreads();

        // ---- S = Q K^T (3-pass split) ----
        float s[8][4];
#pragma unroll
        for (int fn = 0; fn < 8; fn++)
#pragma unroll
            for (int j = 0; j < 4; j++) s[fn][j] = 0.f;

#pragma unroll
        for (int kb = 0; kb < 4; kb++) {
            uint32_t ah[4], al[4], bhf[8][2], blf[8][2], tt[4];
            uint32_t arow = (uint32_t)(wid * 16) + lrow16;
            ldsm4(ah, sbase + QHI_B + arow * 144 + kb * 32 + lchunk);
            ldsm4(al, sbase + QLO_B + arow * 144 + kb * 32 + lchunk);
#pragma unroll
            for (int fb = 0; fb < 4; fb++) {
                uint32_t r = (uint32_t)(fb * 16) + lrow16;
                ldsm4(tt, sbase + KHI_B + r * 144 + kb * 32 + lchunk);
                bhf[2*fb][0]   = tt[0]; bhf[2*fb][1]   = tt[2];
                bhf[2*fb+1][0] = tt[1]; bhf[2*fb+1][1] = tt[3];
                ldsm4(tt, sbase + KLO_B + r * 144 + kb * 32 + lchunk);
                blf[2*fb][0]   = tt[0]; blf[2*fb][1]   = tt[2];
                blf[2*fb+1][0] = tt[1]; blf[2*fb+1][1] = tt[3];
            }
#pragma unroll
            for (int fn = 0; fn < 8; fn++) mma_bf16(s[fn], ah, bhf[fn]);
#pragma unroll
            for (int fn = 0; fn < 8; fn++) mma_bf16(s[fn], al, bhf[fn]);
#pragma unroll
            for (int fn = 0; fn < 8; fn++) mma_bf16(s[fn], ah, blf[fn]);
        }

        // ---- masking (boundary tiles only) ----
        if (jt >= 2 * qt) {
            const int growb = qt * 128 + wid * 16;
            const int colb  = jt * 64 + t2;
#pragma unroll
            for (int fn = 0; fn < 8; fn++) {
                int col = colb + fn * 8;
                if (col     > growb + g)     s[fn][0] = -1e30f;
                if (col + 1 > growb + g)     s[fn][1] = -1e30f;
                if (col     > growb + g + 8) s[fn][2] = -1e30f;
                if (col + 1 > growb + g + 8) s[fn][3] = -1e30f;
            }
        }

        // ---- online softmax (rows g, g+8 of this warp's 16) ----
        float mx0 = -1e30f, mx1 = -1e30f;
#pragma unroll
        for (int fn = 0; fn < 8; fn++) {
            mx0 = fmaxf(mx0, fmaxf(s[fn][0], s[fn][1]));
            mx1 = fmaxf(mx1, fmaxf(s[fn][2], s[fn][3]));
        }
        mx0 = fmaxf(mx0, __shfl_xor_sync(0xffffffffu, mx0, 1));
        mx0 = fmaxf(mx0, __shfl_xor_sync(0xffffffffu, mx0, 2));
        mx1 = fmaxf(mx1, __shfl_xor_sync(0xffffffffu, mx1, 1));
        mx1 = fmaxf(mx1, __shfl_xor_sync(0xffffffffu, mx1, 2));
        const float mn0 = fmaxf(m0, mx0), mn1 = fmaxf(m1, mx1);
        const float sc0 = fast_exp(m0 - mn0), sc1 = fast_exp(m1 - mn1);

        float p[8][4];
        float ps0 = 0.f, ps1 = 0.f;
#pragma unroll
        for (int fn = 0; fn < 8; fn++) {
            p[fn][0] = fast_exp(s[fn][0] - mn0);
            p[fn][1] = fast_exp(s[fn][1] - mn0);
            p[fn][2] = fast_exp(s[fn][2] - mn1);
            p[fn][3] = fast_exp(s[fn][3] - mn1);
            ps0 += p[fn][0] + p[fn][1];
            ps1 += p[fn][2] + p[fn][3];
        }
        ps0 += __shfl_xor_sync(0xffffffffu, ps0, 1);
        ps0 += __shfl_xor_sync(0xffffffffu, ps0, 2);
        ps1 += __shfl_xor_sync(0xffffffffu, ps1, 1);
        ps1 += __shfl_xor_sync(0xffffffffu, ps1, 2);
        l0 = l0 * sc0 + ps0; m0 = mn0;
        l1 = l1 * sc1 + ps1; m1 = mn1;
#pragma unroll
        for (int fn = 0; fn < 8; fn++) {
            O[fn][0] *= sc0; O[fn][1] *= sc0;
            O[fn][2] *= sc1; O[fn][3] *= sc1;
        }

        // ---- P d-frags -> A-frags, 2-term split (registers only) ----
        uint32_t pah[4][4], pal[4][4];
#pragma unroll
        for (int kb = 0; kb < 4; kb++) {
            split2_pack(p[2*kb][0],   p[2*kb][1],   pah[kb][0], pal[kb][0]);
            split2_pack(p[2*kb][2],   p[2*kb][3],   pah[kb][1], pal[kb][1]);
            split2_pack(p[2*kb+1][0], p[2*kb+1][1], pah[kb][2], pal[kb][2]);
            split2_pack(p[2*kb+1][2], p[2*kb+1][3], pah[kb][3], pal[kb][3]);
        }

        // ---- O += P @ V (3-pass: Phi*Vhi + Plo*Vhi + Phi*Vlo) ----
#pragma unroll
        for (int kb = 0; kb < 4; kb++) {
            uint32_t bvh[8][2], bvl[8][2], tt[4];
#pragma unroll
            for (int fb = 0; fb < 4; fb++) {
                uint32_t r = (uint32_t)(fb * 16) + lrow16;
                ldsm4(tt, sbase + VHI_B + r * 144 + kb * 32 + lchunk);
                bvh[2*fb][0]   = tt[0]; bvh[2*fb][1]   = tt[2];
                bvh[2*fb+1][0] = tt[1]; bvh[2*fb+1][1] = tt[3];
                ldsm4(tt, sbase + VLO_B + r * 144 + kb * 32 + lchunk);
                bvl[2*fb][0]   = tt[0]; bvl[2*fb][1]   = tt[2];
                bvl[2*fb+1][0] = tt[1]; bvl[2*fb+1][1] = tt[3];
            }
#pragma unroll
            for (int fn = 0; fn < 8; fn++) mma_bf16(O[fn], pah[kb], bvh[fn]);
#pragma unroll
            for (int fn = 0; fn < 8; fn++) mma_bf16(O[fn], pal[kb], bvh[fn]);
#pragma unroll
            for (int fn = 0; fn < 8; fn++) mma_bf16(O[fn], pah[kb], bvl[fn]);
        }
    }

    // ---- diagonal (k1,v1) bank + final normalize + store ----
    const int r0 = wid * 16 + g, r1 = r0 + 8;
    const size_t rowbase = ((size_t)bh * NS + qt * 128);
    const float* qr0 = g_Q  + (rowbase + r0) * NDH;
    const float* qr1 = g_Q  + (rowbase + r1) * NDH;
    const float* k10 = g_K1 + (rowbase + r0) * NDH;
    const float* k11 = g_K1 + (rowbase + r1) * NDH;
    const int toff = (lane & 3) * 16;
    float d0 = 0.f, d1 = 0.f;
#pragma unroll
    for (int j = 0; j < 16; j += 4) {
        float4 a0 = *(const float4*)&qr0[toff + j];
        float4 b0 = *(const float4*)&k10[toff + j];
        d0 += a0.x*b0.x + a0.y*b0.y + a0.z*b0.z + a0.w*b0.w;
        float4 a1 = *(const float4*)&qr1[toff + j];
        float4 b1 = *(const float4*)&k11[toff + j];
        d1 += a1.x*b1.x + a1.y*b1.y + a1.z*b1.z + a1.w*b1.w;
    }
    d0 += __shfl_xor_sync(0xffffffffu, d0, 1);
    d0 += __shfl_xor_sync(0xffffffffu, d0, 2);
    d1 += __shfl_xor_sync(0xffffffffu, d1, 1);
    d1 += __shfl_xor_sync(0xffffffffu, d1, 2);
    d0 *= 0.125f; d1 *= 0.125f;

    const float mf0 = fmaxf(m0, d0), mf1 = fmaxf(m1, d1);
    const float fc0 = fast_exp(m0 - mf0), fc1 = fast_exp(m1 - mf1);
    const float p20 = fast_exp(d0 - mf0), p21 = fast_exp(d1 - mf1);
    const float inv0 = 1.0f / (l0 * fc0 + p20);
    const float inv1 = 1.0f / (l1 * fc1 + p21);

    const int b = bh >> 4, h = bh & 15;
    const float* v10 = g_V1 + (rowbase + r0) * NDH;
    const float* v11 = g_V1 + (rowbase + r1) * NDH;
    float* o0 = out + ((size_t)(b * NS) + qt * 128 + r0) * ND + h * NDH;
    float* o1 = out + ((size_t)(b * NS) + qt * 128 + r1) * ND + h * NDH;
#pragma unroll
    for (int fn = 0; fn < 8; fn++) {
        const int col = fn * 8 + t2;
        float2 w0 = *(const float2*)&v10[col];
        float2 w1 = *(const float2*)&v11[col];
        float2 r0o, r1o;
        r0o.x = (O[fn][0] * fc0 + p20 * w0.x) * inv0;
        r0o.y = (O[fn][1] * fc0 + p20 * w0.y) * inv0;
        r1o.x = (O[fn][2] * fc1 + p21 * w1.x) * inv1;
        r1o.y = (O[fn][3] * fc1 + p21 * w1.y) * inv1;
        *(float2*)&o0[col] = r0o;
        *(float2*)&o1[col] = r1o;
    }
}

// ---------------------------------------------------------------------------
extern "C" void kernel_launch(void* const* d_in, const int* in_sizes, int n_in,
                              void* d_out, int out_size)
{
    const float* x  = (const float*)d_in[0];
    const float* y  = (const float*)d_in[1];
    const float* wq = (const float*)d_in[2];
    // d_in[3] = wk is UNUSED by the reference (K = y directly)
    const float* wv = (const float*)d_in[4];
    const float* wo = (const float*)d_in[5];

    float* out   = (float*)d_out;          // (B,S,D)    = 4194304 floats
    float* k_ret = out + NELEM;            // (B,H,S,DH) = 4194304 floats

    cudaFuncSetAttribute(attn_mma_kernel,
                         cudaFuncAttributeMaxDynamicSharedMemorySize, ATTN_SMEM);

    gemm3_mma_kernel<<<dim3(8, 32, 3), 256>>>(x, y, wq, wv, wo);
    rope_kernel<<<(NBH * NS * 32) / 256, 256>>>(y, k_ret);
    attn_mma_kernel<<<dim3(NS / 128, NBH), 256, ATTN_SMEM>>>(k_ret, out);
}

// round 7
// speedup vs baseline: 3.8901x; 1.2047x over previous
#include <cuda_runtime.h>
#include <cuda_bf16.h>
#include <math.h>
#include <cstdint>

#define NB 2
#define NS 2048
#define ND 1024
#define NH 16
#define NDH 64
#define NBH (NB*NH)          // 32
#define NTOK (NB*NS)         // 4096
#define NELEM (NTOK*ND)      // 4194304
#define NW (ND*ND)           // 1048576

// fp32 scratch (head-major: [(b*NH+h)*NS + s]*NDH + d)
__device__ float g_Q[NELEM];
__device__ float g_V[NELEM];
__device__ float g_V1[NELEM];
__device__ float g_K1[NELEM];

// Pre-split bf16 operands
__device__ __nv_bfloat16 g_xhi[NELEM], g_xlo[NELEM];
__device__ __nv_bfloat16 g_yhi[NELEM], g_ylo[NELEM];
__device__ __nv_bfloat16 g_wqhi[NW], g_wqlo[NW];
__device__ __nv_bfloat16 g_wvhi[NW], g_wvlo[NW];
__device__ __nv_bfloat16 g_wohi[NW], g_wolo[NW];
// Attention operands (bf16, pre-split; q scaled by 1/8)
__device__ __nv_bfloat16 g_qhi[NELEM], g_qlo[NELEM];
__device__ __nv_bfloat16 g_khi[NELEM], g_klo[NELEM];
__device__ __nv_bfloat16 g_vthi[NELEM], g_vtlo[NELEM];  // [bh][d][s]

// ===========================================================================
// helpers
// ===========================================================================
__device__ __forceinline__ uint32_t smem_u32(const void* p) {
    uint32_t a;
    asm("{ .reg .u64 t; cvta.to.shared.u64 t, %1; cvt.u32.u64 %0, t; }"
        : "=r"(a) : "l"(p));
    return a;
}
__device__ __forceinline__ void ldsm4(uint32_t r[4], uint32_t addr) {
    asm volatile("ldmatrix.sync.aligned.m8n8.x4.shared.b16 {%0,%1,%2,%3}, [%4];"
                 : "=r"(r[0]), "=r"(r[1]), "=r"(r[2]), "=r"(r[3]) : "r"(addr));
}
__device__ __forceinline__ void mma_bf16(float d[4], const uint32_t a[4],
                                         const uint32_t b[2]) {
    asm volatile(
        "mma.sync.aligned.m16n8k16.row.col.f32.bf16.bf16.f32 "
        "{%0,%1,%2,%3}, {%4,%5,%6,%7}, {%8,%9}, {%0,%1,%2,%3};"
        : "+f"(d[0]), "+f"(d[1]), "+f"(d[2]), "+f"(d[3])
        : "r"(a[0]), "r"(a[1]), "r"(a[2]), "r"(a[3]), "r"(b[0]), "r"(b[1]));
}
__device__ __forceinline__ void split4(float4 v, uint2& hi, uint2& lo) {
    __nv_bfloat16 hx = __float2bfloat16_rn(v.x);
    __nv_bfloat16 hy = __float2bfloat16_rn(v.y);
    __nv_bfloat16 hz = __float2bfloat16_rn(v.z);
    __nv_bfloat16 hw = __float2bfloat16_rn(v.w);
    hi.x = (uint32_t)__bfloat16_as_ushort(hx) | ((uint32_t)__bfloat16_as_ushort(hy) << 16);
    hi.y = (uint32_t)__bfloat16_as_ushort(hz) | ((uint32_t)__bfloat16_as_ushort(hw) << 16);
    __nv_bfloat16 lx = __float2bfloat16_rn(v.x - __bfloat162float(hx));
    __nv_bfloat16 ly = __float2bfloat16_rn(v.y - __bfloat162float(hy));
    __nv_bfloat16 lz = __float2bfloat16_rn(v.z - __bfloat162float(hz));
    __nv_bfloat16 lw = __float2bfloat16_rn(v.w - __bfloat162float(hw));
    lo.x = (uint32_t)__bfloat16_as_ushort(lx) | ((uint32_t)__bfloat16_as_ushort(ly) << 16);
    lo.y = (uint32_t)__bfloat16_as_ushort(lz) | ((uint32_t)__bfloat16_as_ushort(lw) << 16);
}
__device__ __forceinline__ void split2_pack(float a, float b,
                                            uint32_t& hi, uint32_t& lo) {
    __nv_bfloat16 ha = __float2bfloat16_rn(a);
    __nv_bfloat16 hb = __float2bfloat16_rn(b);
    hi = (uint32_t)__bfloat16_as_ushort(ha) | ((uint32_t)__bfloat16_as_ushort(hb) << 16);
    __nv_bfloat16 la = __float2bfloat16_rn(a - __bfloat162float(ha));
    __nv_bfloat16 lb = __float2bfloat16_rn(b - __bfloat162float(hb));
    lo = (uint32_t)__bfloat16_as_ushort(la) | ((uint32_t)__bfloat16_as_ushort(lb) << 16);
}
// FFMA-only exp. Valid for x <= ~0; ~2e-6 rel err.
__device__ __forceinline__ float fast_exp(float x) {
    float y = fmaxf(x * 1.4426950408889634f, -126.0f);
    float z = y + 12582912.0f;
    int   n = __float_as_int(z) - 0x4B400000;
    float r = y - (z - 12582912.0f);
    float p = 1.3333558146e-3f;
    p = fmaf(p, r, 9.6181291076e-3f);
    p = fmaf(p, r, 5.5504108664e-2f);
    p = fmaf(p, r, 2.4022650695e-1f);
    p = fmaf(p, r, 6.9314718056e-1f);
    p = fmaf(p, r, 1.0f);
    return p * __int_as_float((n + 127) << 23);
}

// ===========================================================================
// Pre-split: fp32 -> bf16 hi/lo global arrays. which: 0=x 1=y 2=wq 3=wv 4=wo
// ===========================================================================
__global__ __launch_bounds__(256) void presplit_kernel(const float* __restrict__ src,
                                                       int which)
{
    __nv_bfloat16 *hi, *lo;
    switch (which) {
        case 0: hi = g_xhi;  lo = g_xlo;  break;
        case 1: hi = g_yhi;  lo = g_ylo;  break;
        case 2: hi = g_wqhi; lo = g_wqlo; break;
        case 3: hi = g_wvhi; lo = g_wvlo; break;
        default:hi = g_wohi; lo = g_wolo; break;
    }
    const int idx = blockIdx.x * 256 + threadIdx.x;
    float4 v = ((const float4*)src)[idx];
    uint2 h, l; split4(v, h, l);
    ((uint2*)hi)[idx] = h;
    ((uint2*)lo)[idx] = l;
}

// ===========================================================================
// GEMM (mma.sync, pre-split bf16 inputs, double-buffered smem):
// C = A @ W^T, 3-pass split. Block 128x128, 8 warps, k-step 32.
// smem stage: Ahi|Alo|Whi|Wlo, each 128x40 bf16 (10240 B); stage = 40960 B.
// ===========================================================================
#define GSTG_E 20480                    // elems per stage
#define GEMM_SMEM (2*GSTG_E*2)          // 81920 bytes

__global__ __launch_bounds__(256) void gemm3_mma_kernel()
{
    extern __shared__ __align__(16) __nv_bfloat16 smg[];

    const __nv_bfloat16 *Ahi, *Alo, *Whi, *Wlo; float* C;
    switch (blockIdx.z) {
        case 0:  Ahi=g_xhi; Alo=g_xlo; Whi=g_wqhi; Wlo=g_wqlo; C=g_Q;  break;
        case 1:  Ahi=g_yhi; Alo=g_ylo; Whi=g_wvhi; Wlo=g_wvlo; C=g_V;  break;
        default: Ahi=g_xhi; Alo=g_xlo; Whi=g_wohi; Wlo=g_wolo; C=g_V1; break;
    }
    const int m0   = blockIdx.y * 128;
    const int n0   = blockIdx.x * 128;
    const int tid  = threadIdx.x;
    const int lane = tid & 31, wid = tid >> 5;
    const int wm   = wid >> 1, wn = wid & 1;

    const uint32_t sb0 = smem_u32(smg);
    const uint32_t lrow16 = (uint32_t)(lane & 15);
    const uint32_t lchunk = (uint32_t)(lane >> 4) * 16;

    // load mapping: 512 uint4 per array; thread does rows r0, r0+64 at c4
    const int r0 = tid >> 2;          // 0..63
    const int c4 = tid & 3;           // 0..3 (x8 bf16)

    float acc[2][8][4];
#pragma unroll
    for (int i = 0; i < 2; i++)
#pragma unroll
        for (int j = 0; j < 8; j++)
#pragma unroll
            for (int r = 0; r < 4; r++) acc[i][j][r] = 0.f;

    // prologue: chunk 0 -> stage 0
#pragma unroll
    for (int half = 0; half < 2; half++) {
        const int row = r0 + half * 64;
        *(uint4*)&smg[row*40 + c4*8]         = *(const uint4*)&Ahi[(size_t)(m0+row)*ND + c4*8];
        *(uint4*)&smg[5120 + row*40 + c4*8]  = *(const uint4*)&Alo[(size_t)(m0+row)*ND + c4*8];
        *(uint4*)&smg[10240 + row*40 + c4*8] = *(const uint4*)&Whi[(size_t)(n0+row)*ND + c4*8];
        *(uint4*)&smg[15360 + row*40 + c4*8] = *(const uint4*)&Wlo[(size_t)(n0+row)*ND + c4*8];
    }
    __syncthreads();

    uint4 pr[8];
    for (int c = 0; c < 32; c++) {
        if (c < 31) {
            const int k0n = (c + 1) * 32;
#pragma unroll
            for (int half = 0; half < 2; half++) {
                const int row = r0 + half * 64;
                pr[half*4+0] = *(const uint4*)&Ahi[(size_t)(m0+row)*ND + k0n + c4*8];
                pr[half*4+1] = *(const uint4*)&Alo[(size_t)(m0+row)*ND + k0n + c4*8];
                pr[half*4+2] = *(const uint4*)&Whi[(size_t)(n0+row)*ND + k0n + c4*8];
                pr[half*4+3] = *(const uint4*)&Wlo[(size_t)(n0+row)*ND + k0n + c4*8];
            }
        }

        const uint32_t bAh = sb0 + (uint32_t)(c & 1) * 40960;
        const uint32_t bAl = bAh + 10240;
        const uint32_t bWh = bAh + 20480;
        const uint32_t bWl = bAh + 30720;

        {
            const uint32_t kb = lchunk;     // single 32-wide k chunk => 2 k16 slabs
#pragma unroll
            for (int ks = 0; ks < 2; ks++) {
                const uint32_t kbb = (uint32_t)ks * 32 + kb;
                uint32_t ahi[2][4], alo[2][4], bw[8][2], t[4];
#pragma unroll
                for (int fm = 0; fm < 2; fm++) {
                    uint32_t r = (uint32_t)(wm * 32 + fm * 16) + lrow16;
                    ldsm4(ahi[fm], bAh + r * 80 + kbb);
                }
#pragma unroll
                for (int fb = 0; fb < 4; fb++) {
                    uint32_t r = (uint32_t)(wn * 64 + fb * 16) + lrow16;
                    ldsm4(t, bWh + r * 80 + kbb);
                    bw[2*fb][0]   = t[0]; bw[2*fb][1]   = t[2];
                    bw[2*fb+1][0] = t[1]; bw[2*fb+1][1] = t[3];
                }
#pragma unroll
                for (int fm = 0; fm < 2; fm++)
#pragma unroll
                    for (int fn = 0; fn < 8; fn++)
                        mma_bf16(acc[fm][fn], ahi[fm], bw[fn]);
#pragma unroll
                for (int fm = 0; fm < 2; fm++) {
                    uint32_t r = (uint32_t)(wm * 32 + fm * 16) + lrow16;
                    ldsm4(alo[fm], bAl + r * 80 + kbb);
                }
#pragma unroll
                for (int fm = 0; fm < 2; fm++)
#pragma unroll
                    for (int fn = 0; fn < 8; fn++)
                        mma_bf16(acc[fm][fn], alo[fm], bw[fn]);
#pragma unroll
                for (int fb = 0; fb < 4; fb++) {
                    uint32_t r = (uint32_t)(wn * 64 + fb * 16) + lrow16;
                    ldsm4(t, bWl + r * 80 + kbb);
                    bw[2*fb][0]   = t[0]; bw[2*fb][1]   = t[2];
                    bw[2*fb+1][0] = t[1]; bw[2*fb+1][1] = t[3];
                }
#pragma unroll
                for (int fm = 0; fm < 2; fm++)
#pragma unroll
                    for (int fn = 0; fn < 8; fn++)
                        mma_bf16(acc[fm][fn], ahi[fm], bw[fn]);
            }
        }

        if (c < 31) {
            __nv_bfloat16* dst = smg + ((c + 1) & 1) * GSTG_E;
#pragma unroll
            for (int half = 0; half < 2; half++) {
                const int row = r0 + half * 64;
                *(uint4*)&dst[row*40 + c4*8]         = pr[half*4+0];
                *(uint4*)&dst[5120 + row*40 + c4*8]  = pr[half*4+1];
                *(uint4*)&dst[10240 + row*40 + c4*8] = pr[half*4+2];
                *(uint4*)&dst[15360 + row*40 + c4*8] = pr[half*4+3];
            }
            __syncthreads();
        }
    }

    const int g  = lane >> 2;
    const int t2 = (lane & 3) * 2;
    const int bb = m0 >> 11;
    const int h  = blockIdx.x * 2 + wn;
    float* Cb = C + ((size_t)(bb * NH + h) * NS) * NDH;
    const int srow0 = (m0 & (NS - 1)) + wm * 32 + g;
#pragma unroll
    for (int fm = 0; fm < 2; fm++) {
        const int s = srow0 + fm * 16;
#pragma unroll
        for (int fn = 0; fn < 8; fn++) {
            const int d = fn * 8 + t2;
            *(float2*)&Cb[(size_t)s * NDH + d]       = make_float2(acc[fm][fn][0], acc[fm][fn][1]);
            *(float2*)&Cb[(size_t)(s + 8) * NDH + d] = make_float2(acc[fm][fn][2], acc[fm][fn][3]);
        }
    }
}

// ---------------------------------------------------------------------------
// RoPE: Q in-place + qhi/qlo (x0.125); k_roped -> k_ret + khi/klo;
// k1 -> g_K1.
// ---------------------------------------------------------------------------
__global__ __launch_bounds__(256) void rope_kernel(
    const float* __restrict__ y, float* __restrict__ k_ret)
{
    const int idx = blockIdx.x * 256 + threadIdx.x;
    const int i   = idx & 31;
    const int s   = (idx >> 5) & (NS - 1);
    const int bh  = idx >> 16;
    const int b   = bh >> 4, h = bh & 15;

    const float LOG2_THETA = 13.287712379549449f;
    const float freq = exp2f(-(float)i * (LOG2_THETA * (1.0f / 32.0f)));
    float sn, cs;
    sincosf((float)s * freq, &sn, &cs);

    const size_t base = ((size_t)bh * NS + s) * NDH;

    float q1 = g_Q[base + i], q2 = g_Q[base + i + 32];
    float qn1 = q1 * cs - q2 * sn;
    float qn2 = q2 * cs + q1 * sn;
    g_Q[base + i]      = qn1;
    g_Q[base + i + 32] = qn2;
    {
        float a1 = qn1 * 0.125f, a2 = qn2 * 0.125f;
        __nv_bfloat16 h1 = __float2bfloat16_rn(a1);
        __nv_bfloat16 h2 = __float2bfloat16_rn(a2);
        g_qhi[base + i]      = h1;
        g_qhi[base + i + 32] = h2;
        g_qlo[base + i]      = __float2bfloat16_rn(a1 - __bfloat162float(h1));
        g_qlo[base + i + 32] = __float2bfloat16_rn(a2 - __bfloat162float(h2));
    }

    const float* yrow = y + ((size_t)b * NS + s) * ND + h * NDH;
    float u1 = yrow[i], u2 = yrow[i + 32];
    float kr1 = u1 * cs - u2 * sn;
    float kr2 = u2 * cs + u1 * sn;
    k_ret[base + i]      = kr1;
    k_ret[base + i + 32] = kr2;
    {
        __nv_bfloat16 h1 = __float2bfloat16_rn(kr1);
        __nv_bfloat16 h2 = __float2bfloat16_rn(kr2);
        g_khi[base + i]      = h1;
        g_khi[base + i + 32] = h2;
        g_klo[base + i]      = __float2bfloat16_rn(kr1 - __bfloat162float(h1));
        g_klo[base + i + 32] = __float2bfloat16_rn(kr2 - __bfloat162float(h2));
    }
    g_K1[base + i]      = kr1 * cs - kr2 * sn;
    g_K1[base + i + 32] = kr2 * cs + kr1 * sn;
}

// ---------------------------------------------------------------------------
// V transpose + split: g_V [bh][s][d] fp32 -> vthi/vtlo [bh][d][s] bf16.
// Block handles one (bh, 64-s chunk).
// ---------------------------------------------------------------------------
__global__ __launch_bounds__(256) void vtrans_kernel()
{
    __shared__ __nv_bfloat16 th[64][72];
    __shared__ __nv_bfloat16 tl[64][72];
    const int bh = blockIdx.y;
    const int s0 = blockIdx.x * 64;
    const int tid = threadIdx.x;

#pragma unroll
    for (int i = 0; i < 4; i++) {
        int idx = tid + i * 256;          // 1024 float4
        int sr = idx >> 4, c4 = idx & 15;
        float4 v = *(const float4*)&g_V[((size_t)bh * NS + s0 + sr) * NDH + c4 * 4];
        float vals[4] = {v.x, v.y, v.z, v.w};
#pragma unroll
        for (int j = 0; j < 4; j++) {
            int d = c4 * 4 + j;
            __nv_bfloat16 hh = __float2bfloat16_rn(vals[j]);
            th[d][sr] = hh;
            tl[d][sr] = __float2bfloat16_rn(vals[j] - __bfloat162float(hh));
        }
    }
    __syncthreads();

#pragma unroll
    for (int i = 0; i < 4; i++) {
        int idx = tid + i * 256;          // 1024 uint4: arr(2) x d(64) x c8(8)
        int arr = idx >> 9;
        int j = idx & 511;
        int d = j >> 3, c8 = j & 7;
        uint4 v = arr ? *(uint4*)&tl[d][c8 * 8] : *(uint4*)&th[d][c8 * 8];
        __nv_bfloat16* dst = arr ? g_vtlo : g_vthi;
        *(uint4*)&dst[((size_t)bh * NDH + d) * NS + s0 + c8 * 8] = v;
    }
}

// ===========================================================================
// MMA flash attention + diagonal (k1,v1) bank. Pre-split bf16 operands.
// ===========================================================================
#define QHI_B 0
#define QLO_B 18432
#define KHI_B 36864
#define KLO_B 46080
#define VHI_B 55296
#define VLO_B 64512
#define ATTN_SMEM 73728

__global__ __launch_bounds__(256) void attn_mma_kernel(float* __restrict__ out)
{
    extern __shared__ __align__(16) char smraw[];
    __nv_bfloat16* sb = (__nv_bfloat16*)smraw;

    const int qt  = (NS / 128 - 1) - blockIdx.x;   // heavy tiles first
    const int bh  = blockIdx.y;
    const int tid = threadIdx.x;
    const int lane = tid & 31, wid = tid >> 5;
    const int g = lane >> 2, t2 = (lane & 3) * 2;
    const uint32_t lrow16 = (uint32_t)(lane & 15);
    const uint32_t lchunk = (uint32_t)(lane >> 4) * 16;
    const uint32_t sbase = smem_u32(sb);

    // ---- Q tiles (pre-scaled, pre-split) ----
    const size_t qbase = ((size_t)bh * NS + qt * 128) * NDH;
#pragma unroll
    for (int i = 0; i < 4; i++) {
        int idx = tid + i * 256;          // 1024 uint4 per array
        int row = idx >> 3, c8 = idx & 7;
        *(uint4*)((char*)sb + QHI_B + row * 144 + c8 * 16) =
            *(const uint4*)&g_qhi[qbase + row * NDH + c8 * 8];
        *(uint4*)((char*)sb + QLO_B + row * 144 + c8 * 16) =
            *(const uint4*)&g_qlo[qbase + row * NDH + c8 * 8];
    }

    float m0 = -1e30f, m1 = -1e30f, l0 = 0.f, l1 = 0.f;
    float O[8][4];
#pragma unroll
    for (int fn = 0; fn < 8; fn++)
#pragma unroll
        for (int j = 0; j < 4; j++) O[fn][j] = 0.f;

    const int jt_end = 2 * qt + 1;
    for (int jt = 0; jt <= jt_end; jt++) {
        __syncthreads();
#pragma unroll
        for (int i = 0; i < 2; i++) {
            int idx = tid + i * 256;      // 512 uint4 per array
            int row = idx >> 3, c8 = idx & 7;
            size_t kb = ((size_t)bh * NS + jt * 64 + row) * NDH + c8 * 8;
            *(uint4*)((char*)sb + KHI_B + row * 144 + c8 * 16) = *(const uint4*)&g_khi[kb];
            *(uint4*)((char*)sb + KLO_B + row * 144 + c8 * 16) = *(const uint4*)&g_klo[kb];
            size_t vb = ((size_t)bh * NDH + row) * NS + jt * 64 + c8 * 8;
            *(uint4*)((char*)sb + VHI_B + row * 144 + c8 * 16) = *(const uint4*)&g_vthi[vb];
            *(uint4*)((char*)sb + VLO_B + row * 144 + c8 * 16) = *(const uint4*)&g_vtlo[vb];
        }
        __syncthreads();

        // ---- S = Q K^T (3-pass split) ----
        float s[8][4];
#pragma unroll
        for (int fn = 0; fn < 8; fn++)
#pragma unroll
            for (int j = 0; j < 4; j++) s[fn][j] = 0.f;

#pragma unroll
        for (int kb = 0; kb < 4; kb++) {
            uint32_t ah[4], al[4], bhf[8][2], blf[8][2], tt[4];
            uint32_t arow = (uint32_t)(wid * 16) + lrow16;
            ldsm4(ah, sbase + QHI_B + arow * 144 + kb * 32 + lchunk);
            ldsm4(al, sbase + QLO_B + arow * 144 + kb * 32 + lchunk);
#pragma unroll
            for (int fb = 0; fb < 4; fb++) {
                uint32_t r = (uint32_t)(fb * 16) + lrow16;
                ldsm4(tt, sbase + KHI_B + r * 144 + kb * 32 + lchunk);
                bhf[2*fb][0]   = tt[0]; bhf[2*fb][1]   = tt[2];
                bhf[2*fb+1][0] = tt[1]; bhf[2*fb+1][1] = tt[3];
                ldsm4(tt, sbase + KLO_B + r * 144 + kb * 32 + lchunk);
                blf[2*fb][0]   = tt[0]; blf[2*fb][1]   = tt[2];
                blf[2*fb+1][0] = tt[1]; blf[2*fb+1][1] = tt[3];
            }
#pragma unroll
            for (int fn = 0; fn < 8; fn++) mma_bf16(s[fn], ah, bhf[fn]);
#pragma unroll
            for (int fn = 0; fn < 8; fn++) mma_bf16(s[fn], al, bhf[fn]);
#pragma unroll
            for (int fn = 0; fn < 8; fn++) mma_bf16(s[fn], ah, blf[fn]);
        }

        // ---- masking (boundary tiles only) ----
        if (jt >= 2 * qt) {
            const int growb = qt * 128 + wid * 16;
            const int colb  = jt * 64 + t2;
#pragma unroll
            for (int fn = 0; fn < 8; fn++) {
                int col = colb + fn * 8;
                if (col     > growb + g)     s[fn][0] = -1e30f;
                if (col + 1 > growb + g)     s[fn][1] = -1e30f;
                if (col     > growb + g + 8) s[fn][2] = -1e30f;
                if (col + 1 > growb + g + 8) s[fn][3] = -1e30f;
            }
        }

        // ---- online softmax ----
        float mx0 = -1e30f, mx1 = -1e30f;
#pragma unroll
        for (int fn = 0; fn < 8; fn++) {
            mx0 = fmaxf(mx0, fmaxf(s[fn][0], s[fn][1]));
            mx1 = fmaxf(mx1, fmaxf(s[fn][2], s[fn][3]));
        }
        mx0 = fmaxf(mx0, __shfl_xor_sync(0xffffffffu, mx0, 1));
        mx0 = fmaxf(mx0, __shfl_xor_sync(0xffffffffu, mx0, 2));
        mx1 = fmaxf(mx1, __shfl_xor_sync(0xffffffffu, mx1, 1));
        mx1 = fmaxf(mx1, __shfl_xor_sync(0xffffffffu, mx1, 2));
        const float mn0 = fmaxf(m0, mx0), mn1 = fmaxf(m1, mx1);
        const float sc0 = fast_exp(m0 - mn0), sc1 = fast_exp(m1 - mn1);

        float p[8][4];
        float ps0 = 0.f, ps1 = 0.f;
#pragma unroll
        for (int fn = 0; fn < 8; fn++) {
            p[fn][0] = fast_exp(s[fn][0] - mn0);
            p[fn][1] = fast_exp(s[fn][1] - mn0);
            p[fn][2] = fast_exp(s[fn][2] - mn1);
            p[fn][3] = fast_exp(s[fn][3] - mn1);
            ps0 += p[fn][0] + p[fn][1];
            ps1 += p[fn][2] + p[fn][3];
        }
        ps0 += __shfl_xor_sync(0xffffffffu, ps0, 1);
        ps0 += __shfl_xor_sync(0xffffffffu, ps0, 2);
        ps1 += __shfl_xor_sync(0xffffffffu, ps1, 1);
        ps1 += __shfl_xor_sync(0xffffffffu, ps1, 2);
        l0 = l0 * sc0 + ps0; m0 = mn0;
        l1 = l1 * sc1 + ps1; m1 = mn1;
#pragma unroll
        for (int fn = 0; fn < 8; fn++) {
            O[fn][0] *= sc0; O[fn][1] *= sc0;
            O[fn][2] *= sc1; O[fn][3] *= sc1;
        }

        // ---- P -> A-frags, 2-term split ----
        uint32_t pah[4][4], pal[4][4];
#pragma unroll
        for (int kb = 0; kb < 4; kb++) {
            split2_pack(p[2*kb][0],   p[2*kb][1],   pah[kb][0], pal[kb][0]);
            split2_pack(p[2*kb][2],   p[2*kb][3],   pah[kb][1], pal[kb][1]);
            split2_pack(p[2*kb+1][0], p[2*kb+1][1], pah[kb][2], pal[kb][2]);
            split2_pack(p[2*kb+1][2], p[2*kb+1][3], pah[kb][3], pal[kb][3]);
        }

        // ---- O += P @ V (3-pass) ----
#pragma unroll
        for (int kb = 0; kb < 4; kb++) {
            uint32_t bvh[8][2], bvl[8][2], tt[4];
#pragma unroll
            for (int fb = 0; fb < 4; fb++) {
                uint32_t r = (uint32_t)(fb * 16) + lrow16;
                ldsm4(tt, sbase + VHI_B + r * 144 + kb * 32 + lchunk);
                bvh[2*fb][0]   = tt[0]; bvh[2*fb][1]   = tt[2];
                bvh[2*fb+1][0] = tt[1]; bvh[2*fb+1][1] = tt[3];
                ldsm4(tt, sbase + VLO_B + r * 144 + kb * 32 + lchunk);
                bvl[2*fb][0]   = tt[0]; bvl[2*fb][1]   = tt[2];
                bvl[2*fb+1][0] = tt[1]; bvl[2*fb+1][1] = tt[3];
            }
#pragma unroll
            for (int fn = 0; fn < 8; fn++) mma_bf16(O[fn], pah[kb], bvh[fn]);
#pragma unroll
            for (int fn = 0; fn < 8; fn++) mma_bf16(O[fn], pal[kb], bvh[fn]);
#pragma unroll
            for (int fn = 0; fn < 8; fn++) mma_bf16(O[fn], pah[kb], bvl[fn]);
        }
    }

    // ---- diagonal (k1,v1) bank + normalize + store ----
    const int r0 = wid * 16 + g, r1 = r0 + 8;
    const size_t rowbase = ((size_t)bh * NS + qt * 128);
    const float* qr0 = g_Q  + (rowbase + r0) * NDH;
    const float* qr1 = g_Q  + (rowbase + r1) * NDH;
    const float* k10 = g_K1 + (rowbase + r0) * NDH;
    const float* k11 = g_K1 + (rowbase + r1) * NDH;
    const int toff = (lane & 3) * 16;
    float d0 = 0.f, d1 = 0.f;
#pragma unroll
    for (int j = 0; j < 16; j += 4) {
        float4 a0 = *(const float4*)&qr0[toff + j];
        float4 b0 = *(const float4*)&k10[toff + j];
        d0 += a0.x*b0.x + a0.y*b0.y + a0.z*b0.z + a0.w*b0.w;
        float4 a1 = *(const float4*)&qr1[toff + j];
        float4 b1 = *(const float4*)&k11[toff + j];
        d1 += a1.x*b1.x + a1.y*b1.y + a1.z*b1.z + a1.w*b1.w;
    }
    d0 += __shfl_xor_sync(0xffffffffu, d0, 1);
    d0 += __shfl_xor_sync(0xffffffffu, d0, 2);
    d1 += __shfl_xor_sync(0xffffffffu, d1, 1);
    d1 += __shfl_xor_sync(0xffffffffu, d1, 2);
    d0 *= 0.125f; d1 *= 0.125f;

    const float mf0 = fmaxf(m0, d0), mf1 = fmaxf(m1, d1);
    const float fc0 = fast_exp(m0 - mf0), fc1 = fast_exp(m1 - mf1);
    const float p20 = fast_exp(d0 - mf0), p21 = fast_exp(d1 - mf1);
    const float inv0 = 1.0f / (l0 * fc0 + p20);
    const float inv1 = 1.0f / (l1 * fc1 + p21);

    const int b = bh >> 4, h = bh & 15;
    const float* v10 = g_V1 + (rowbase + r0) * NDH;
    const float* v11 = g_V1 + (rowbase + r1) * NDH;
    float* o0 = out + ((size_t)(b * NS) + qt * 128 + r0) * ND + h * NDH;
    float* o1 = out + ((size_t)(b * NS) + qt * 128 + r1) * ND + h * NDH;
#pragma unroll
    for (int fn = 0; fn < 8; fn++) {
        const int col = fn * 8 + t2;
        float2 w0 = *(const float2*)&v10[col];
        float2 w1 = *(const float2*)&v11[col];
        float2 r0o, r1o;
        r0o.x = (O[fn][0] * fc0 + p20 * w0.x) * inv0;
        r0o.y = (O[fn][1] * fc0 + p20 * w0.y) * inv0;
        r1o.x = (O[fn][2] * fc1 + p21 * w1.x) * inv1;
        r1o.y = (O[fn][3] * fc1 + p21 * w1.y) * inv1;
        *(float2*)&o0[col] = r0o;
        *(float2*)&o1[col] = r1o;
    }
}

// ---------------------------------------------------------------------------
extern "C" void kernel_launch(void* const* d_in, const int* in_sizes, int n_in,
                              void* d_out, int out_size)
{
    const float* x  = (const float*)d_in[0];
    const float* y  = (const float*)d_in[1];
    const float* wq = (const float*)d_in[2];
    // d_in[3] = wk is UNUSED by the reference (K = y directly)
    const float* wv = (const float*)d_in[4];
    const float* wo = (const float*)d_in[5];

    float* out   = (float*)d_out;          // (B,S,D)    = 4194304 floats
    float* k_ret = out + NELEM;            // (B,H,S,DH) = 4194304 floats

    cudaFuncSetAttribute(gemm3_mma_kernel,
                         cudaFuncAttributeMaxDynamicSharedMemorySize, GEMM_SMEM);
    cudaFuncSetAttribute(attn_mma_kernel,
                         cudaFuncAttributeMaxDynamicSharedMemorySize, ATTN_SMEM);

    presplit_kernel<<<NELEM / 1024, 256>>>(x, 0);
    presplit_kernel<<<NELEM / 1024, 256>>>(y, 1);
    presplit_kernel<<<NW / 1024, 256>>>(wq, 2);
    presplit_kernel<<<NW / 1024, 256>>>(wv, 3);
    presplit_kernel<<<NW / 1024, 256>>>(wo, 4);

    gemm3_mma_kernel<<<dim3(8, 32, 3), 256, GEMM_SMEM>>>();
    rope_kernel<<<(NBH * NS * 32) / 256, 256>>>(y, k_ret);
    vtrans_kernel<<<dim3(NS / 64, NBH), 256>>>();
    attn_mma_kernel<<<dim3(NS / 128, NBH), 256, ATTN_SMEM>>>(out);
}

// round 8
// speedup vs baseline: 3.9314x; 1.0106x over previous
#include <cuda_runtime.h>
#include <cuda_bf16.h>
#include <math.h>
#include <cstdint>

#define NB 2
#define NS 2048
#define ND 1024
#define NH 16
#define NDH 64
#define NBH (NB*NH)          // 32
#define NTOK (NB*NS)         // 4096
#define NELEM (NTOK*ND)      // 4194304
#define NW (ND*ND)           // 1048576

// fp32 scratch (head-major: [(b*NH+h)*NS + s]*NDH + d)
__device__ float g_Q[NELEM];
__device__ float g_V[NELEM];
__device__ float g_V1[NELEM];
__device__ float g_K1[NELEM];

// Pre-split bf16 operands
__device__ __nv_bfloat16 g_xhi[NELEM], g_xlo[NELEM];
__device__ __nv_bfloat16 g_yhi[NELEM], g_ylo[NELEM];
__device__ __nv_bfloat16 g_wqhi[NW], g_wqlo[NW];
__device__ __nv_bfloat16 g_wvhi[NW], g_wvlo[NW];
__device__ __nv_bfloat16 g_wohi[NW], g_wolo[NW];
// Attention operands (bf16, pre-split; q scaled by 1/8)
__device__ __nv_bfloat16 g_qhi[NELEM], g_qlo[NELEM];
__device__ __nv_bfloat16 g_khi[NELEM], g_klo[NELEM];
__device__ __nv_bfloat16 g_vthi[NELEM], g_vtlo[NELEM];  // [bh][d][s]

// ===========================================================================
// helpers
// ===========================================================================
__device__ __forceinline__ uint32_t smem_u32(const void* p) {
    uint32_t a;
    asm("{ .reg .u64 t; cvta.to.shared.u64 t, %1; cvt.u32.u64 %0, t; }"
        : "=r"(a) : "l"(p));
    return a;
}
__device__ __forceinline__ void ldsm4(uint32_t r[4], uint32_t addr) {
    asm volatile("ldmatrix.sync.aligned.m8n8.x4.shared.b16 {%0,%1,%2,%3}, [%4];"
                 : "=r"(r[0]), "=r"(r[1]), "=r"(r[2]), "=r"(r[3]) : "r"(addr));
}
__device__ __forceinline__ void mma_bf16(float d[4], const uint32_t a[4],
                                         const uint32_t b[2]) {
    asm volatile(
        "mma.sync.aligned.m16n8k16.row.col.f32.bf16.bf16.f32 "
        "{%0,%1,%2,%3}, {%4,%5,%6,%7}, {%8,%9}, {%0,%1,%2,%3};"
        : "+f"(d[0]), "+f"(d[1]), "+f"(d[2]), "+f"(d[3])
        : "r"(a[0]), "r"(a[1]), "r"(a[2]), "r"(a[3]), "r"(b[0]), "r"(b[1]));
}
__device__ __forceinline__ void cp_async16(uint32_t saddr, const void* g) {
    asm volatile("cp.async.cg.shared.global [%0], [%1], 16;"
                 :: "r"(saddr), "l"(g));
}
__device__ __forceinline__ void cp_commit() {
    asm volatile("cp.async.commit_group;" ::: "memory");
}
__device__ __forceinline__ void cp_wait0() {
    asm volatile("cp.async.wait_group 0;" ::: "memory");
}
__device__ __forceinline__ void split4(float4 v, uint2& hi, uint2& lo) {
    __nv_bfloat16 hx = __float2bfloat16_rn(v.x);
    __nv_bfloat16 hy = __float2bfloat16_rn(v.y);
    __nv_bfloat16 hz = __float2bfloat16_rn(v.z);
    __nv_bfloat16 hw = __float2bfloat16_rn(v.w);
    hi.x = (uint32_t)__bfloat16_as_ushort(hx) | ((uint32_t)__bfloat16_as_ushort(hy) << 16);
    hi.y = (uint32_t)__bfloat16_as_ushort(hz) | ((uint32_t)__bfloat16_as_ushort(hw) << 16);
    __nv_bfloat16 lx = __float2bfloat16_rn(v.x - __bfloat162float(hx));
    __nv_bfloat16 ly = __float2bfloat16_rn(v.y - __bfloat162float(hy));
    __nv_bfloat16 lz = __float2bfloat16_rn(v.z - __bfloat162float(hz));
    __nv_bfloat16 lw = __float2bfloat16_rn(v.w - __bfloat162float(hw));
    lo.x = (uint32_t)__bfloat16_as_ushort(lx) | ((uint32_t)__bfloat16_as_ushort(ly) << 16);
    lo.y = (uint32_t)__bfloat16_as_ushort(lz) | ((uint32_t)__bfloat16_as_ushort(lw) << 16);
}
__device__ __forceinline__ void split2_pack(float a, float b,
                                            uint32_t& hi, uint32_t& lo) {
    __nv_bfloat16 ha = __float2bfloat16_rn(a);
    __nv_bfloat16 hb = __float2bfloat16_rn(b);
    hi = (uint32_t)__bfloat16_as_ushort(ha) | ((uint32_t)__bfloat16_as_ushort(hb) << 16);
    __nv_bfloat16 la = __float2bfloat16_rn(a - __bfloat162float(ha));
    __nv_bfloat16 lb = __float2bfloat16_rn(b - __bfloat162float(hb));
    lo = (uint32_t)__bfloat16_as_ushort(la) | ((uint32_t)__bfloat16_as_ushort(lb) << 16);
}
// FFMA-only exp. Valid for x <= ~0; ~2e-6 rel err.
__device__ __forceinline__ float fast_exp(float x) {
    float y = fmaxf(x * 1.4426950408889634f, -126.0f);
    float z = y + 12582912.0f;
    int   n = __float_as_int(z) - 0x4B400000;
    float r = y - (z - 12582912.0f);
    float p = 1.3333558146e-3f;
    p = fmaf(p, r, 9.6181291076e-3f);
    p = fmaf(p, r, 5.5504108664e-2f);
    p = fmaf(p, r, 2.4022650695e-1f);
    p = fmaf(p, r, 6.9314718056e-1f);
    p = fmaf(p, r, 1.0f);
    return p * __int_as_float((n + 127) << 23);
}

// ===========================================================================
// Pre-split: fp32 -> bf16 hi/lo global arrays. which: 0=x 1=y 2=wq 3=wv 4=wo
// ===========================================================================
__global__ __launch_bounds__(256) void presplit_kernel(const float* __restrict__ src,
                                                       int which)
{
    __nv_bfloat16 *hi, *lo;
    switch (which) {
        case 0: hi = g_xhi;  lo = g_xlo;  break;
        case 1: hi = g_yhi;  lo = g_ylo;  break;
        case 2: hi = g_wqhi; lo = g_wqlo; break;
        case 3: hi = g_wvhi; lo = g_wvlo; break;
        default:hi = g_wohi; lo = g_wolo; break;
    }
    const int idx = blockIdx.x * 256 + threadIdx.x;
    float4 v = ((const float4*)src)[idx];
    uint2 h, l; split4(v, h, l);
    ((uint2*)hi)[idx] = h;
    ((uint2*)lo)[idx] = l;
}

// ===========================================================================
// GEMM (mma.sync, pre-split bf16 inputs, double-buffered smem):
// C = A @ W^T, 3-pass split. Block 128x128, 8 warps, k-step 32.
// ===========================================================================
#define GSTG_E 20480                    // elems per stage
#define GEMM_SMEM (2*GSTG_E*2)          // 81920 bytes

__global__ __launch_bounds__(256) void gemm3_mma_kernel()
{
    extern __shared__ __align__(16) __nv_bfloat16 smg[];

    const __nv_bfloat16 *Ahi, *Alo, *Whi, *Wlo; float* C;
    switch (blockIdx.z) {
        case 0:  Ahi=g_xhi; Alo=g_xlo; Whi=g_wqhi; Wlo=g_wqlo; C=g_Q;  break;
        case 1:  Ahi=g_yhi; Alo=g_ylo; Whi=g_wvhi; Wlo=g_wvlo; C=g_V;  break;
        default: Ahi=g_xhi; Alo=g_xlo; Whi=g_wohi; Wlo=g_wolo; C=g_V1; break;
    }
    const int m0   = blockIdx.y * 128;
    const int n0   = blockIdx.x * 128;
    const int tid  = threadIdx.x;
    const int lane = tid & 31, wid = tid >> 5;
    const int wm   = wid >> 1, wn = wid & 1;

    const uint32_t sb0 = smem_u32(smg);
    const uint32_t lrow16 = (uint32_t)(lane & 15);
    const uint32_t lchunk = (uint32_t)(lane >> 4) * 16;

    const int r0 = tid >> 2;          // 0..63
    const int c4 = tid & 3;           // 0..3 (x8 bf16)

    float acc[2][8][4];
#pragma unroll
    for (int i = 0; i < 2; i++)
#pragma unroll
        for (int j = 0; j < 8; j++)
#pragma unroll
            for (int r = 0; r < 4; r++) acc[i][j][r] = 0.f;

#pragma unroll
    for (int half = 0; half < 2; half++) {
        const int row = r0 + half * 64;
        *(uint4*)&smg[row*40 + c4*8]         = *(const uint4*)&Ahi[(size_t)(m0+row)*ND + c4*8];
        *(uint4*)&smg[5120 + row*40 + c4*8]  = *(const uint4*)&Alo[(size_t)(m0+row)*ND + c4*8];
        *(uint4*)&smg[10240 + row*40 + c4*8] = *(const uint4*)&Whi[(size_t)(n0+row)*ND + c4*8];
        *(uint4*)&smg[15360 + row*40 + c4*8] = *(const uint4*)&Wlo[(size_t)(n0+row)*ND + c4*8];
    }
    __syncthreads();

    uint4 pr[8];
    for (int c = 0; c < 32; c++) {
        if (c < 31) {
            const int k0n = (c + 1) * 32;
#pragma unroll
            for (int half = 0; half < 2; half++) {
                const int row = r0 + half * 64;
                pr[half*4+0] = *(const uint4*)&Ahi[(size_t)(m0+row)*ND + k0n + c4*8];
                pr[half*4+1] = *(const uint4*)&Alo[(size_t)(m0+row)*ND + k0n + c4*8];
                pr[half*4+2] = *(const uint4*)&Whi[(size_t)(n0+row)*ND + k0n + c4*8];
                pr[half*4+3] = *(const uint4*)&Wlo[(size_t)(n0+row)*ND + k0n + c4*8];
            }
        }

        const uint32_t bAh = sb0 + (uint32_t)(c & 1) * 40960;
        const uint32_t bAl = bAh + 10240;
        const uint32_t bWh = bAh + 20480;
        const uint32_t bWl = bAh + 30720;

#pragma unroll
        for (int ks = 0; ks < 2; ks++) {
            const uint32_t kbb = (uint32_t)ks * 32 + lchunk;
            uint32_t ahi[2][4], alo[2][4], bw[8][2], t[4];
#pragma unroll
            for (int fm = 0; fm < 2; fm++) {
                uint32_t r = (uint32_t)(wm * 32 + fm * 16) + lrow16;
                ldsm4(ahi[fm], bAh + r * 80 + kbb);
            }
#pragma unroll
            for (int fb = 0; fb < 4; fb++) {
                uint32_t r = (uint32_t)(wn * 64 + fb * 16) + lrow16;
                ldsm4(t, bWh + r * 80 + kbb);
                bw[2*fb][0]   = t[0]; bw[2*fb][1]   = t[2];
                bw[2*fb+1][0] = t[1]; bw[2*fb+1][1] = t[3];
            }
#pragma unroll
            for (int fm = 0; fm < 2; fm++)
#pragma unroll
                for (int fn = 0; fn < 8; fn++)
                    mma_bf16(acc[fm][fn], ahi[fm], bw[fn]);
#pragma unroll
            for (int fm = 0; fm < 2; fm++) {
                uint32_t r = (uint32_t)(wm * 32 + fm * 16) + lrow16;
                ldsm4(alo[fm], bAl + r * 80 + kbb);
            }
#pragma unroll
            for (int fm = 0; fm < 2; fm++)
#pragma unroll
                for (int fn = 0; fn < 8; fn++)
                    mma_bf16(acc[fm][fn], alo[fm], bw[fn]);
#pragma unroll
            for (int fb = 0; fb < 4; fb++) {
                uint32_t r = (uint32_t)(wn * 64 + fb * 16) + lrow16;
                ldsm4(t, bWl + r * 80 + kbb);
                bw[2*fb][0]   = t[0]; bw[2*fb][1]   = t[2];
                bw[2*fb+1][0] = t[1]; bw[2*fb+1][1] = t[3];
            }
#pragma unroll
            for (int fm = 0; fm < 2; fm++)
#pragma unroll
                for (int fn = 0; fn < 8; fn++)
                    mma_bf16(acc[fm][fn], ahi[fm], bw[fn]);
        }

        if (c < 31) {
            __nv_bfloat16* dst = smg + ((c + 1) & 1) * GSTG_E;
#pragma unroll
            for (int half = 0; half < 2; half++) {
                const int row = r0 + half * 64;
                *(uint4*)&dst[row*40 + c4*8]         = pr[half*4+0];
                *(uint4*)&dst[5120 + row*40 + c4*8]  = pr[half*4+1];
                *(uint4*)&dst[10240 + row*40 + c4*8] = pr[half*4+2];
                *(uint4*)&dst[15360 + row*40 + c4*8] = pr[half*4+3];
            }
            __syncthreads();
        }
    }

    const int g  = lane >> 2;
    const int t2 = (lane & 3) * 2;
    const int bb = m0 >> 11;
    const int h  = blockIdx.x * 2 + wn;
    float* Cb = C + ((size_t)(bb * NH + h) * NS) * NDH;
    const int srow0 = (m0 & (NS - 1)) + wm * 32 + g;
#pragma unroll
    for (int fm = 0; fm < 2; fm++) {
        const int s = srow0 + fm * 16;
#pragma unroll
        for (int fn = 0; fn < 8; fn++) {
            const int d = fn * 8 + t2;
            *(float2*)&Cb[(size_t)s * NDH + d]       = make_float2(acc[fm][fn][0], acc[fm][fn][1]);
            *(float2*)&Cb[(size_t)(s + 8) * NDH + d] = make_float2(acc[fm][fn][2], acc[fm][fn][3]);
        }
    }
}

// ---------------------------------------------------------------------------
// RoPE: Q in-place + qhi/qlo (x0.125); k_roped -> k_ret + khi/klo; k1 -> g_K1.
// ---------------------------------------------------------------------------
__global__ __launch_bounds__(256) void rope_kernel(
    const float* __restrict__ y, float* __restrict__ k_ret)
{
    const int idx = blockIdx.x * 256 + threadIdx.x;
    const int i   = idx & 31;
    const int s   = (idx >> 5) & (NS - 1);
    const int bh  = idx >> 16;
    const int b   = bh >> 4, h = bh & 15;

    const float LOG2_THETA = 13.287712379549449f;
    const float freq = exp2f(-(float)i * (LOG2_THETA * (1.0f / 32.0f)));
    float sn, cs;
    sincosf((float)s * freq, &sn, &cs);

    const size_t base = ((size_t)bh * NS + s) * NDH;

    float q1 = g_Q[base + i], q2 = g_Q[base + i + 32];
    float qn1 = q1 * cs - q2 * sn;
    float qn2 = q2 * cs + q1 * sn;
    g_Q[base + i]      = qn1;
    g_Q[base + i + 32] = qn2;
    {
        float a1 = qn1 * 0.125f, a2 = qn2 * 0.125f;
        __nv_bfloat16 h1 = __float2bfloat16_rn(a1);
        __nv_bfloat16 h2 = __float2bfloat16_rn(a2);
        g_qhi[base + i]      = h1;
        g_qhi[base + i + 32] = h2;
        g_qlo[base + i]      = __float2bfloat16_rn(a1 - __bfloat162float(h1));
        g_qlo[base + i + 32] = __float2bfloat16_rn(a2 - __bfloat162float(h2));
    }

    const float* yrow = y + ((size_t)b * NS + s) * ND + h * NDH;
    float u1 = yrow[i], u2 = yrow[i + 32];
    float kr1 = u1 * cs - u2 * sn;
    float kr2 = u2 * cs + u1 * sn;
    k_ret[base + i]      = kr1;
    k_ret[base + i + 32] = kr2;
    {
        __nv_bfloat16 h1 = __float2bfloat16_rn(kr1);
        __nv_bfloat16 h2 = __float2bfloat16_rn(kr2);
        g_khi[base + i]      = h1;
        g_khi[base + i + 32] = h2;
        g_klo[base + i]      = __float2bfloat16_rn(kr1 - __bfloat162float(h1));
        g_klo[base + i + 32] = __float2bfloat16_rn(kr2 - __bfloat162float(h2));
    }
    g_K1[base + i]      = kr1 * cs - kr2 * sn;
    g_K1[base + i + 32] = kr2 * cs + kr1 * sn;
}

// ---------------------------------------------------------------------------
// V transpose + split: g_V [bh][s][d] fp32 -> vthi/vtlo [bh][d][s] bf16.
// ---------------------------------------------------------------------------
__global__ __launch_bounds__(256) void vtrans_kernel()
{
    __shared__ __nv_bfloat16 th[64][72];
    __shared__ __nv_bfloat16 tl[64][72];
    const int bh = blockIdx.y;
    const int s0 = blockIdx.x * 64;
    const int tid = threadIdx.x;

#pragma unroll
    for (int i = 0; i < 4; i++) {
        int idx = tid + i * 256;
        int sr = idx >> 4, c4 = idx & 15;
        float4 v = *(const float4*)&g_V[((size_t)bh * NS + s0 + sr) * NDH + c4 * 4];
        float vals[4] = {v.x, v.y, v.z, v.w};
#pragma unroll
        for (int j = 0; j < 4; j++) {
            int d = c4 * 4 + j;
            __nv_bfloat16 hh = __float2bfloat16_rn(vals[j]);
            th[d][sr] = hh;
            tl[d][sr] = __float2bfloat16_rn(vals[j] - __bfloat162float(hh));
        }
    }
    __syncthreads();

#pragma unroll
    for (int i = 0; i < 4; i++) {
        int idx = tid + i * 256;
        int arr = idx >> 9;
        int j = idx & 511;
        int d = j >> 3, c8 = j & 7;
        uint4 v = arr ? *(uint4*)&tl[d][c8 * 8] : *(uint4*)&th[d][c8 * 8];
        __nv_bfloat16* dst = arr ? g_vtlo : g_vthi;
        *(uint4*)&dst[((size_t)bh * NDH + d) * NS + s0 + c8 * 8] = v;
    }
}

// ===========================================================================
// MMA flash attention + diagonal (k1,v1) bank.
// cp.async double-buffered KV stages; one barrier per KV tile.
// smem: Q (QHI 0, QLO 18432) + 2 stages @ 36864 (KHI+0 KLO+9216 VHI+18432 VLO+27648)
// ===========================================================================
#define QHI_B 0
#define QLO_B 18432
#define STG_B 36864
#define STG_SZ 36864
#define ATTN_SMEM (STG_B + 2*STG_SZ)    // 110592

__global__ __launch_bounds__(256) void attn_mma_kernel(float* __restrict__ out)
{
    extern __shared__ __align__(16) char smraw[];
    __nv_bfloat16* sb = (__nv_bfloat16*)smraw;

    const int qt  = (NS / 128 - 1) - blockIdx.x;   // heavy tiles first
    const int bh  = blockIdx.y;
    const int tid = threadIdx.x;
    const int lane = tid & 31, wid = tid >> 5;
    const int g = lane >> 2, t2 = (lane & 3) * 2;
    const uint32_t lrow16 = (uint32_t)(lane & 15);
    const uint32_t lchunk = (uint32_t)(lane >> 4) * 16;
    const uint32_t sbase = smem_u32(sb);

    // cp.async per-thread addresses for KV staging
    const int srow = tid >> 3, sc8 = tid & 7;      // rows 0..31 (+32 on i=1)

    // ---- Q tiles (pre-scaled, pre-split) ----
    const size_t qbase = ((size_t)bh * NS + qt * 128) * NDH;
#pragma unroll
    for (int i = 0; i < 4; i++) {
        int idx = tid + i * 256;
        int row = idx >> 3, c8 = idx & 7;
        *(uint4*)((char*)sb + QHI_B + row * 144 + c8 * 16) =
            *(const uint4*)&g_qhi[qbase + row * NDH + c8 * 8];
        *(uint4*)((char*)sb + QLO_B + row * 144 + c8 * 16) =
            *(const uint4*)&g_qlo[qbase + row * NDH + c8 * 8];
    }

    float m0 = -1e30f, m1 = -1e30f, l0 = 0.f, l1 = 0.f;
    float O[8][4];
#pragma unroll
    for (int fn = 0; fn < 8; fn++)
#pragma unroll
        for (int j = 0; j < 4; j++) O[fn][j] = 0.f;

    const int jt_end = 2 * qt + 1;

    // issue KV tile jt into stage st
    auto issue_tile = [&](int jt, int st) {
        const uint32_t stb = sbase + STG_B + (uint32_t)st * STG_SZ;
#pragma unroll
        for (int i = 0; i < 2; i++) {
            const int row = srow + i * 32;
            const uint32_t so = (uint32_t)(row * 144 + sc8 * 16);
            const size_t kb = ((size_t)bh * NS + jt * 64 + row) * NDH + sc8 * 8;
            cp_async16(stb + so,         &g_khi[kb]);
            cp_async16(stb + 9216 + so,  &g_klo[kb]);
            const size_t vb = ((size_t)bh * NDH + row) * NS + jt * 64 + sc8 * 8;
            cp_async16(stb + 18432 + so, &g_vthi[vb]);
            cp_async16(stb + 27648 + so, &g_vtlo[vb]);
        }
        cp_commit();
    };

    issue_tile(0, 0);

    for (int jt = 0; jt <= jt_end; jt++) {
        cp_wait0();
        __syncthreads();                 // stage (jt&1) visible to all; prev reads done
        if (jt < jt_end) issue_tile(jt + 1, (jt + 1) & 1);

        const uint32_t stb = sbase + STG_B + (uint32_t)(jt & 1) * STG_SZ;
        const uint32_t bKH = stb, bKL = stb + 9216;
        const uint32_t bVH = stb + 18432, bVL = stb + 27648;

        // ---- S = Q K^T (3-pass split) ----
        float s[8][4];
#pragma unroll
        for (int fn = 0; fn < 8; fn++)
#pragma unroll
            for (int j = 0; j < 4; j++) s[fn][j] = 0.f;

#pragma unroll
        for (int kb = 0; kb < 4; kb++) {
            uint32_t ah[4], al[4], bhf[8][2], blf[8][2], tt[4];
            uint32_t arow = (uint32_t)(wid * 16) + lrow16;
            ldsm4(ah, sbase + QHI_B + arow * 144 + kb * 32 + lchunk);
            ldsm4(al, sbase + QLO_B + arow * 144 + kb * 32 + lchunk);
#pragma unroll
            for (int fb = 0; fb < 4; fb++) {
                uint32_t r = (uint32_t)(fb * 16) + lrow16;
                ldsm4(tt, bKH + r * 144 + kb * 32 + lchunk);
                bhf[2*fb][0]   = tt[0]; bhf[2*fb][1]   = tt[2];
                bhf[2*fb+1][0] = tt[1]; bhf[2*fb+1][1] = tt[3];
                ldsm4(tt, bKL + r * 144 + kb * 32 + lchunk);
                blf[2*fb][0]   = tt[0]; blf[2*fb][1]   = tt[2];
                blf[2*fb+1][0] = tt[1]; blf[2*fb+1][1] = tt[3];
            }
#pragma unroll
            for (int fn = 0; fn < 8; fn++) mma_bf16(s[fn], ah, bhf[fn]);
#pragma unroll
            for (int fn = 0; fn < 8; fn++) mma_bf16(s[fn], al, bhf[fn]);
#pragma unroll
            for (int fn = 0; fn < 8; fn++) mma_bf16(s[fn], ah, blf[fn]);
        }

        // ---- masking (boundary tiles only) ----
        if (jt >= 2 * qt) {
            const int growb = qt * 128 + wid * 16;
            const int colb  = jt * 64 + t2;
#pragma unroll
            for (int fn = 0; fn < 8; fn++) {
                int col = colb + fn * 8;
                if (col     > growb + g)     s[fn][0] = -1e30f;
                if (col + 1 > growb + g)     s[fn][1] = -1e30f;
                if (col     > growb + g + 8) s[fn][2] = -1e30f;
                if (col + 1 > growb + g + 8) s[fn][3] = -1e30f;
            }
        }

        // ---- online softmax ----
        float mx0 = -1e30f, mx1 = -1e30f;
#pragma unroll
        for (int fn = 0; fn < 8; fn++) {
            mx0 = fmaxf(mx0, fmaxf(s[fn][0], s[fn][1]));
            mx1 = fmaxf(mx1, fmaxf(s[fn][2], s[fn][3]));
        }
        mx0 = fmaxf(mx0, __shfl_xor_sync(0xffffffffu, mx0, 1));
        mx0 = fmaxf(mx0, __shfl_xor_sync(0xffffffffu, mx0, 2));
        mx1 = fmaxf(mx1, __shfl_xor_sync(0xffffffffu, mx1, 1));
        mx1 = fmaxf(mx1, __shfl_xor_sync(0xffffffffu, mx1, 2));
        const float mn0 = fmaxf(m0, mx0), mn1 = fmaxf(m1, mx1);
        const float sc0 = fast_exp(m0 - mn0), sc1 = fast_exp(m1 - mn1);

        float p[8][4];
        float ps0 = 0.f, ps1 = 0.f;
#pragma unroll
        for (int fn = 0; fn < 8; fn++) {
            p[fn][0] = fast_exp(s[fn][0] - mn0);
            p[fn][1] = fast_exp(s[fn][1] - mn0);
            p[fn][2] = fast_exp(s[fn][2] - mn1);
            p[fn][3] = fast_exp(s[fn][3] - mn1);
            ps0 += p[fn][0] + p[fn][1];
            ps1 += p[fn][2] + p[fn][3];
        }
        ps0 += __shfl_xor_sync(0xffffffffu, ps0, 1);
        ps0 += __shfl_xor_sync(0xffffffffu, ps0, 2);
        ps1 += __shfl_xor_sync(0xffffffffu, ps1, 1);
        ps1 += __shfl_xor_sync(0xffffffffu, ps1, 2);
        l0 = l0 * sc0 + ps0; m0 = mn0;
        l1 = l1 * sc1 + ps1; m1 = mn1;
#pragma unroll
        for (int fn = 0; fn < 8; fn++) {
            O[fn][0] *= sc0; O[fn][1] *= sc0;
            O[fn][2] *= sc1; O[fn][3] *= sc1;
        }

        // ---- P -> A-frags, 2-term split ----
        uint32_t pah[4][4], pal[4][4];
#pragma unroll
        for (int kb = 0; kb < 4; kb++) {
            split2_pack(p[2*kb][0],   p[2*kb][1],   pah[kb][0], pal[kb][0]);
            split2_pack(p[2*kb][2],   p[2*kb][3],   pah[kb][1], pal[kb][1]);
            split2_pack(p[2*kb+1][0], p[2*kb+1][1], pah[kb][2], pal[kb][2]);
            split2_pack(p[2*kb+1][2], p[2*kb+1][3], pah[kb][3], pal[kb][3]);
        }

        // ---- O += P @ V (3-pass) ----
#pragma unroll
        for (int kb = 0; kb < 4; kb++) {
            uint32_t bvh[8][2], bvl[8][2], tt[4];
#pragma unroll
            for (int fb = 0; fb < 4; fb++) {
                uint32_t r = (uint32_t)(fb * 16) + lrow16;
                ldsm4(tt, bVH + r * 144 + kb * 32 + lchunk);
                bvh[2*fb][0]   = tt[0]; bvh[2*fb][1]   = tt[2];
                bvh[2*fb+1][0] = tt[1]; bvh[2*fb+1][1] = tt[3];
                ldsm4(tt, bVL + r * 144 + kb * 32 + lchunk);
                bvl[2*fb][0]   = tt[0]; bvl[2*fb][1]   = tt[2];
                bvl[2*fb+1][0] = tt[1]; bvl[2*fb+1][1] = tt[3];
            }
#pragma unroll
            for (int fn = 0; fn < 8; fn++) mma_bf16(O[fn], pah[kb], bvh[fn]);
#pragma unroll
            for (int fn = 0; fn < 8; fn++) mma_bf16(O[fn], pal[kb], bvh[fn]);
#pragma unroll
            for (int fn = 0; fn < 8; fn++) mma_bf16(O[fn], pah[kb], bvl[fn]);
        }
    }

    // ---- diagonal (k1,v1) bank + normalize + store ----
    const int r0 = wid * 16 + g, r1 = r0 + 8;
    const size_t rowbase = ((size_t)bh * NS + qt * 128);
    const float* qr0 = g_Q  + (rowbase + r0) * NDH;
    const float* qr1 = g_Q  + (rowbase + r1) * NDH;
    const float* k10 = g_K1 + (rowbase + r0) * NDH;
    const float* k11 = g_K1 + (rowbase + r1) * NDH;
    const int toff = (lane & 3) * 16;
    float d0 = 0.f, d1 = 0.f;
#pragma unroll
    for (int j = 0; j < 16; j += 4) {
        float4 a0 = *(const float4*)&qr0[toff + j];
        float4 b0 = *(const float4*)&k10[toff + j];
        d0 += a0.x*b0.x + a0.y*b0.y + a0.z*b0.z + a0.w*b0.w;
        float4 a1 = *(const float4*)&qr1[toff + j];
        float4 b1 = *(const float4*)&k11[toff + j];
        d1 += a1.x*b1.x + a1.y*b1.y + a1.z*b1.z + a1.w*b1.w;
    }
    d0 += __shfl_xor_sync(0xffffffffu, d0, 1);
    d0 += __shfl_xor_sync(0xffffffffu, d0, 2);
    d1 += __shfl_xor_sync(0xffffffffu, d1, 1);
    d1 += __shfl_xor_sync(0xffffffffu, d1, 2);
    d0 *= 0.125f; d1 *= 0.125f;

    const float mf0 = fmaxf(m0, d0), mf1 = fmaxf(m1, d1);
    const float fc0 = fast_exp(m0 - mf0), fc1 = fast_exp(m1 - mf1);
    const float p20 = fast_exp(d0 - mf0), p21 = fast_exp(d1 - mf1);
    const float inv0 = 1.0f / (l0 * fc0 + p20);
    const float inv1 = 1.0f / (l1 * fc1 + p21);

    const int b = bh >> 4, h = bh & 15;
    const float* v10 = g_V1 + (rowbase + r0) * NDH;
    const float* v11 = g_V1 + (rowbase + r1) * NDH;
    float* o0 = out + ((size_t)(b * NS) + qt * 128 + r0) * ND + h * NDH;
    float* o1 = out + ((size_t)(b * NS) + qt * 128 + r1) * ND + h * NDH;
#pragma unroll
    for (int fn = 0; fn < 8; fn++) {
        const int col = fn * 8 + t2;
        float2 w0 = *(const float2*)&v10[col];
        float2 w1 = *(const float2*)&v11[col];
        float2 r0o, r1o;
        r0o.x = (O[fn][0] * fc0 + p20 * w0.x) * inv0;
        r0o.y = (O[fn][1] * fc0 + p20 * w0.y) * inv0;
        r1o.x = (O[fn][2] * fc1 + p21 * w1.x) * inv1;
        r1o.y = (O[fn][3] * fc1 + p21 * w1.y) * inv1;
        *(float2*)&o0[col] = r0o;
        *(float2*)&o1[col] = r1o;
    }
}

// ---------------------------------------------------------------------------
extern "C" void kernel_launch(void* const* d_in, const int* in_sizes, int n_in,
                              void* d_out, int out_size)
{
    const float* x  = (const float*)d_in[0];
    const float* y  = (const float*)d_in[1];
    const float* wq = (const float*)d_in[2];
    // d_in[3] = wk is UNUSED by the reference (K = y directly)
    const float* wv = (const float*)d_in[4];
    const float* wo = (const float*)d_in[5];

    float* out   = (float*)d_out;          // (B,S,D)    = 4194304 floats
    float* k_ret = out + NELEM;            // (B,H,S,DH) = 4194304 floats

    cudaFuncSetAttribute(gemm3_mma_kernel,
                         cudaFuncAttributeMaxDynamicSharedMemorySize, GEMM_SMEM);
    cudaFuncSetAttribute(attn_mma_kernel,
                         cudaFuncAttributeMaxDynamicSharedMemorySize, ATTN_SMEM);

    presplit_kernel<<<NELEM / 1024, 256>>>(x, 0);
    presplit_kernel<<<NELEM / 1024, 256>>>(y, 1);
    presplit_kernel<<<NW / 1024, 256>>>(wq, 2);
    presplit_kernel<<<NW / 1024, 256>>>(wv, 3);
    presplit_kernel<<<NW / 1024, 256>>>(wo, 4);

    gemm3_mma_kernel<<<dim3(8, 32, 3), 256, GEMM_SMEM>>>();
    rope_kernel<<<(NBH * NS * 32) / 256, 256>>>(y, k_ret);
    vtrans_kernel<<<dim3(NS / 64, NBH), 256>>>();
    attn_mma_kernel<<<dim3(NS / 128, NBH), 256, ATTN_SMEM>>>(out);
}